// round 2
// baseline (speedup 1.0000x reference)
#include <cuda_runtime.h>

#define FD 128
#define TM 128
#define NTHREADS 256

// Scratch (allocation-free rule: __device__ globals)
__device__ float g_embed[500096 * FD];   // embed[N][F]
__device__ float g_kvec[4096 * FD];      // per-batch k vector
__device__ float g_pred[4096];           // segment sum of embed_total
__device__ float g_cnt[4096];            // atoms per molecule

__device__ __forceinline__ float siluf(float v) {
    return v / (1.0f + expf(-v));
}
__device__ __forceinline__ float softplusf(float v) {
    return fmaxf(v, 0.0f) + log1pf(expf(-fabsf(v)));
}

// ---------------------------------------------------------------------------
// prep: kvec[b*F+f] = |E[b]|*Wk[f] + bk[f]; zero accumulators (every call)
// ---------------------------------------------------------------------------
__global__ void prep_kernel(const float* __restrict__ E,
                            const float* __restrict__ Wk,
                            const float* __restrict__ bk, int B) {
    int i = blockIdx.x * blockDim.x + threadIdx.x;
    if (i < B * FD) {
        int b = i >> 7, f = i & 127;
        g_kvec[i] = fabsf(E[b]) * Wk[f] + bk[f];
    }
    if (i < B) { g_pred[i] = 0.0f; g_cnt[i] = 0.0f; }
}

// ---------------------------------------------------------------------------
// pass1: q = x@Wq + bq ; embed = softplus(kvec[seg]*q) -> g_embed
//        segment-sum(embed rowsums) -> g_pred, counts -> g_cnt
// block: 256 threads, 128 rows, smem = Wq(64KB) + x^T tile(66KB)
// ---------------------------------------------------------------------------
__global__ __launch_bounds__(NTHREADS)
void pass1_kernel(const float* __restrict__ x,
                  const int* __restrict__ seg,
                  const float* __restrict__ Wq,
                  const float* __restrict__ bq, int N, int B) {
    extern __shared__ float sm[];
    float* Ws = sm;                 // [128][128] row-major (k-major for B)
    float* At = sm + FD * FD;       // [128][132] : At[k][m] = x[m][k]
    __shared__ float rowsum[TM];
    __shared__ int segs[TM];

    const int tid = threadIdx.x;
    const int m0 = blockIdx.x * TM;

    #pragma unroll 4
    for (int i = tid; i < (FD * FD) / 4; i += NTHREADS)
        ((float4*)Ws)[i] = ((const float4*)Wq)[i];

    for (int i = tid; i < (TM * FD) / 4; i += NTHREADS) {
        int idx = i << 2;
        int r = idx >> 7;
        int c = idx & 127;
        int gr = min(m0 + r, N - 1);
        float4 v = *(const float4*)(x + (size_t)gr * FD + c);
        At[(c + 0) * 132 + r] = v.x;
        At[(c + 1) * 132 + r] = v.y;
        At[(c + 2) * 132 + r] = v.z;
        At[(c + 3) * 132 + r] = v.w;
    }
    if (tid < TM) {
        rowsum[tid] = 0.0f;
        int gr = min(m0 + tid, N - 1);
        int sb = seg[gr];
        segs[tid] = min(max(sb, 0), B - 1);   // defensive clamp
    }
    __syncthreads();

    const int ty = tid >> 4, tx = tid & 15;
    const int r0 = ty * 8, c0 = tx * 8;

    float acc[8][8];
    #pragma unroll
    for (int i = 0; i < 8; i++)
        #pragma unroll
        for (int j = 0; j < 8; j++) acc[i][j] = 0.0f;

    #pragma unroll 8
    for (int k = 0; k < FD; k++) {
        float a[8], b[8];
        *(float4*)(a)     = *(float4*)(At + k * 132 + r0);
        *(float4*)(a + 4) = *(float4*)(At + k * 132 + r0 + 4);
        *(float4*)(b)     = *(float4*)(Ws + k * FD + c0);
        *(float4*)(b + 4) = *(float4*)(Ws + k * FD + c0 + 4);
        #pragma unroll
        for (int i = 0; i < 8; i++)
            #pragma unroll
            for (int j = 0; j < 8; j++)
                acc[i][j] = fmaf(a[i], b[j], acc[i][j]);
    }

    float bqv[8];
    *(float4*)(bqv)     = *(const float4*)(bq + c0);
    *(float4*)(bqv + 4) = *(const float4*)(bq + c0 + 4);

    #pragma unroll
    for (int i = 0; i < 8; i++) {
        int lr = r0 + i;
        int gr = m0 + lr;
        int sb = segs[lr];
        const float* kv = g_kvec + (size_t)sb * FD + c0;
        float e[8];
        float rs = 0.0f;
        #pragma unroll
        for (int j = 0; j < 8; j++) {
            float t = kv[j] * (acc[i][j] + bqv[j]);
            float v = softplusf(t);
            e[j] = v;
            rs += v;
        }
        atomicAdd(&rowsum[lr], rs);
        if (gr < N) {
            *(float4*)(g_embed + (size_t)gr * FD + c0)     = *(float4*)(e);
            *(float4*)(g_embed + (size_t)gr * FD + c0 + 4) = *(float4*)(e + 4);
        }
    }
    __syncthreads();

    // batch_seg is sorted: run-length reduce inside the block, few global atomics
    if (tid < TM) {
        bool head = (tid == 0) || (segs[tid] != segs[tid - 1]);
        if (head && (m0 + tid) < N) {
            int sb = segs[tid];
            float s = 0.0f, c = 0.0f;
            for (int j = tid; j < TM && segs[j] == sb && (m0 + j) < N; j++) {
                s += rowsum[j];
                c += 1.0f;
            }
            atomicAdd(&g_pred[sb], s);
            atomicAdd(&g_cnt[sb], c);
        }
    }
}

// ---------------------------------------------------------------------------
// pass2: scale = embed + d/F ; h = silu(scale)@W1+b1 ; h = silu(h)@W2+b2
//        out = scale + h   (both GEMMs chained in shared memory)
// smem = W(64KB) + S scale tile(64KB) + act tile(66KB)
// ---------------------------------------------------------------------------
__global__ __launch_bounds__(NTHREADS)
void pass2_kernel(const float* __restrict__ E,
                  const int* __restrict__ seg,
                  const float* __restrict__ W1, const float* __restrict__ b1,
                  const float* __restrict__ W2, const float* __restrict__ b2,
                  float* __restrict__ out, int N, int B) {
    extern __shared__ float sm[];
    float* Ws = sm;                 // [128][128] weights (W1 then W2)
    float* S  = sm + FD * FD;       // [128][128] scale_embed tile
    float* At = S + FD * FD;        // GEMM1: [k][m] stride 132; GEMM2: [m][k] stride 129
    __shared__ float dval[TM];

    const int tid = threadIdx.x;
    const int m0 = blockIdx.x * TM;

    if (tid < TM) {
        int gr = min(m0 + tid, N - 1);
        int sb = min(max(seg[gr], 0), B - 1);
        dval[tid] = (E[sb] - g_pred[sb]) / g_cnt[sb] * (1.0f / 128.0f);
    }
    #pragma unroll 4
    for (int i = tid; i < (FD * FD) / 4; i += NTHREADS)
        ((float4*)Ws)[i] = ((const float4*)W1)[i];
    __syncthreads();

    for (int i = tid; i < (TM * FD) / 4; i += NTHREADS) {
        int idx = i << 2;
        int r = idx >> 7;
        int c = idx & 127;
        int gr = min(m0 + r, N - 1);
        float4 v = *(const float4*)(g_embed + (size_t)gr * FD + c);
        float d = dval[r];
        v.x += d; v.y += d; v.z += d; v.w += d;
        *(float4*)(S + r * FD + c) = v;
        At[(c + 0) * 132 + r] = siluf(v.x);
        At[(c + 1) * 132 + r] = siluf(v.y);
        At[(c + 2) * 132 + r] = siluf(v.z);
        At[(c + 3) * 132 + r] = siluf(v.w);
    }
    __syncthreads();

    const int ty = tid >> 4, tx = tid & 15;
    const int r0 = ty * 8, c0 = tx * 8;

    float acc[8][8];
    #pragma unroll
    for (int i = 0; i < 8; i++)
        #pragma unroll
        for (int j = 0; j < 8; j++) acc[i][j] = 0.0f;

    #pragma unroll 8
    for (int k = 0; k < FD; k++) {
        float a[8], b[8];
        *(float4*)(a)     = *(float4*)(At + k * 132 + r0);
        *(float4*)(a + 4) = *(float4*)(At + k * 132 + r0 + 4);
        *(float4*)(b)     = *(float4*)(Ws + k * FD + c0);
        *(float4*)(b + 4) = *(float4*)(Ws + k * FD + c0 + 4);
        #pragma unroll
        for (int i = 0; i < 8; i++)
            #pragma unroll
            for (int j = 0; j < 8; j++)
                acc[i][j] = fmaf(a[i], b[j], acc[i][j]);
    }

    float b1v[8];
    *(float4*)(b1v)     = *(const float4*)(b1 + c0);
    *(float4*)(b1v + 4) = *(const float4*)(b1 + c0 + 4);

    __syncthreads();  // everyone done reading At (and Ws) for GEMM1

    // silu(h1) -> At as row-major [m][k] with stride 129 (conflict-light)
    #pragma unroll
    for (int i = 0; i < 8; i++)
        #pragma unroll
        for (int j = 0; j < 8; j++)
            At[(r0 + i) * 129 + c0 + j] = siluf(acc[i][j] + b1v[j]);

    #pragma unroll 4
    for (int i = tid; i < (FD * FD) / 4; i += NTHREADS)
        ((float4*)Ws)[i] = ((const float4*)W2)[i];
    __syncthreads();

    float acc2[8][8];
    #pragma unroll
    for (int i = 0; i < 8; i++)
        #pragma unroll
        for (int j = 0; j < 8; j++) acc2[i][j] = 0.0f;

    #pragma unroll 4
    for (int k = 0; k < FD; k++) {
        float a[8], b[8];
        #pragma unroll
        for (int i = 0; i < 8; i++) a[i] = At[(r0 + i) * 129 + k];
        *(float4*)(b)     = *(float4*)(Ws + k * FD + c0);
        *(float4*)(b + 4) = *(float4*)(Ws + k * FD + c0 + 4);
        #pragma unroll
        for (int i = 0; i < 8; i++)
            #pragma unroll
            for (int j = 0; j < 8; j++)
                acc2[i][j] = fmaf(a[i], b[j], acc2[i][j]);
    }

    float b2v[8];
    *(float4*)(b2v)     = *(const float4*)(b2 + c0);
    *(float4*)(b2v + 4) = *(const float4*)(b2 + c0 + 4);

    #pragma unroll
    for (int i = 0; i < 8; i++) {
        int gr = m0 + r0 + i;
        if (gr < N) {
            float o[8];
            #pragma unroll
            for (int j = 0; j < 8; j++)
                o[j] = S[(r0 + i) * FD + c0 + j] + acc2[i][j] + b2v[j];
            *(float4*)(out + (size_t)gr * FD + c0)     = *(float4*)(o);
            *(float4*)(out + (size_t)gr * FD + c0 + 4) = *(float4*)(o + 4);
        }
    }
}

// ---------------------------------------------------------------------------
extern "C" void kernel_launch(void* const* d_in, const int* in_sizes, int n_in,
                              void* d_out, int out_size) {
    const float* x   = (const float*)d_in[0];
    const float* E   = (const float*)d_in[1];
    // d_in[2] = num_batch scalar (unused; B from in_sizes[1])
    const int*   seg = (const int*)d_in[3];   // jax x64 disabled -> int32
    const float* Wq  = (const float*)d_in[4];
    const float* bq  = (const float*)d_in[5];
    const float* Wk  = (const float*)d_in[6];
    const float* bk  = (const float*)d_in[7];
    const float* W1  = (const float*)d_in[8];
    const float* b1  = (const float*)d_in[9];
    const float* W2  = (const float*)d_in[10];
    const float* b2  = (const float*)d_in[11];
    float* out = (float*)d_out;

    const int N = in_sizes[0] / FD;
    const int B = in_sizes[1];

    const int smem1 = (FD * FD + FD * 132) * (int)sizeof(float);            // 133120
    const int smem2 = (FD * FD + FD * FD + FD * 132) * (int)sizeof(float);  // 198656
    cudaFuncSetAttribute(pass1_kernel, cudaFuncAttributeMaxDynamicSharedMemorySize, smem1);
    cudaFuncSetAttribute(pass2_kernel, cudaFuncAttributeMaxDynamicSharedMemorySize, smem2);

    prep_kernel<<<(B * FD + 255) / 256, 256>>>(E, Wk, bk, B);

    const int nblk = (N + TM - 1) / TM;
    pass1_kernel<<<nblk, NTHREADS, smem1>>>(x, seg, Wq, bq, N, B);
    pass2_kernel<<<nblk, NTHREADS, smem2>>>(E, seg, W1, b1, W2, b2, out, N, B);
}

// round 4
// speedup vs baseline: 1.6547x; 1.6547x over previous
#include <cuda_runtime.h>
#include <cstdint>

#define FD 128
#define TM 128            // rows per CTA
#define NT 256            // threads per CTA (8 warps: 4 row-groups x 2 col-groups)
#define LDW 132           // smem row stride in words (conflict-free for frag loads)

// ---------------- device scratch ----------------
__device__ float g_pred[4096];
__device__ float g_cnt[4096];
__device__ uint32_t g_WqT[FD * FD];  // [n][k] transposed, tf32-RN-rounded
__device__ uint32_t g_W1T[FD * FD];
__device__ uint32_t g_W2T[FD * FD];

// ---------------- helpers ----------------
__device__ __forceinline__ uint32_t f2tf32(float f) {
    uint32_t r;
    asm("cvt.rna.tf32.f32 %0, %1;" : "=r"(r) : "f"(f));
    return r;
}
__device__ __forceinline__ float softplus_fast(float t) {
    return fmaxf(t, 0.0f) + __logf(1.0f + __expf(-fabsf(t)));
}
__device__ __forceinline__ float silu_fast(float v) {
    return __fdividef(v, 1.0f + __expf(-v));
}
__device__ __forceinline__ void mma8(float& c0, float& c1, float& c2, float& c3,
                                     uint32_t a0, uint32_t a1, uint32_t a2, uint32_t a3,
                                     uint32_t b0, uint32_t b1) {
    asm volatile("mma.sync.aligned.m16n8k8.row.col.f32.tf32.tf32.f32 "
                 "{%0,%1,%2,%3}, {%4,%5,%6,%7}, {%8,%9}, {%0,%1,%2,%3};"
                 : "+f"(c0), "+f"(c1), "+f"(c2), "+f"(c3)
                 : "r"(a0), "r"(a1), "r"(a2), "r"(a3), "r"(b0), "r"(b1));
}

// 128x128x128 GEMM tile: As[m][k] (stride LDW), Bs[n][k] (stride LDW), both tf32 bits.
// Warp computes 32x64: acc[2 mfrag][8 nfrag][4].
__device__ __forceinline__ void gemm_tile(const uint32_t* __restrict__ As,
                                          const uint32_t* __restrict__ Bs,
                                          float acc[2][8][4], int mw, int nw, int lane) {
    #pragma unroll
    for (int i = 0; i < 2; i++)
        #pragma unroll
        for (int j = 0; j < 8; j++)
            #pragma unroll
            for (int e = 0; e < 4; e++) acc[i][j][e] = 0.0f;

    const int g = lane >> 2, t = lane & 3;
    #pragma unroll 1
    for (int ks = 0; ks < 16; ks++) {
        const int k0 = ks * 8 + t;
        uint32_t a[2][4];
        #pragma unroll
        for (int i = 0; i < 2; i++) {
            int r = mw + 16 * i + g;
            a[i][0] = As[r * LDW + k0];
            a[i][1] = As[(r + 8) * LDW + k0];
            a[i][2] = As[r * LDW + k0 + 4];
            a[i][3] = As[(r + 8) * LDW + k0 + 4];
        }
        #pragma unroll
        for (int j = 0; j < 8; j++) {
            int n = nw + 8 * j + g;
            uint32_t b0 = Bs[n * LDW + k0];
            uint32_t b1 = Bs[n * LDW + k0 + 4];
            mma8(acc[0][j][0], acc[0][j][1], acc[0][j][2], acc[0][j][3],
                 a[0][0], a[0][1], a[0][2], a[0][3], b0, b1);
            mma8(acc[1][j][0], acc[1][j][1], acc[1][j][2], acc[1][j][3],
                 a[1][0], a[1][1], a[1][2], a[1][3], b0, b1);
        }
    }
}

// ---------------- prep: transpose + RN-round weights, zero accumulators ----------------
__global__ void prep_kernel(const float* __restrict__ Wq, const float* __restrict__ W1,
                            const float* __restrict__ W2, int B) {
    int i = blockIdx.x * blockDim.x + threadIdx.x;
    if (i < FD * FD) {
        int k = i >> 7, n = i & 127;          // W[k][n] -> WT[n][k]
        g_WqT[n * FD + k] = f2tf32(Wq[i]);
        g_W1T[n * FD + k] = f2tf32(W1[i]);
        g_W2T[n * FD + k] = f2tf32(W2[i]);
    }
    if (i < B) { g_pred[i] = 0.0f; g_cnt[i] = 0.0f; }
}

// ---------------- pass1: GEMM q + softplus + segment sums (nothing stored per-atom) ----
__global__ __launch_bounds__(NT, 1)
void pass1_kernel(const float* __restrict__ x, const int* __restrict__ seg,
                  const float* __restrict__ E, const float* __restrict__ bq,
                  const float* __restrict__ Wk, const float* __restrict__ bk,
                  int N, int B) {
    extern __shared__ uint32_t dyn[];
    uint32_t* As = dyn;                  // [128][LDW]
    uint32_t* Bs = dyn + TM * LDW;       // [128][LDW]
    __shared__ float rowsum[TM], eabs_sm[TM];
    __shared__ int segs[TM];
    __shared__ float s_bq[FD], s_Wk[FD], s_bk[FD];

    const int tid = threadIdx.x, wid = tid >> 5, lane = tid & 31;
    const int m0 = blockIdx.x * TM;

    if (tid < TM) {
        int gr = min(m0 + tid, N - 1);
        int sb = seg[gr]; sb = min(max(sb, 0), B - 1);
        segs[tid] = sb;
        eabs_sm[tid] = fabsf(E[sb]);
        rowsum[tid] = 0.0f;
        s_bq[tid] = bq[tid]; s_Wk[tid] = Wk[tid]; s_bk[tid] = bk[tid];
    }

    for (int i = tid; i < TM * 32; i += NT) {
        int r = i >> 5, c = (i & 31) << 2;
        *(uint4*)(Bs + r * LDW + c) = ((const uint4*)g_WqT)[i];
        int gr = min(m0 + r, N - 1);
        float4 v = *(const float4*)(x + (size_t)gr * FD + c);
        uint4 u = make_uint4(f2tf32(v.x), f2tf32(v.y), f2tf32(v.z), f2tf32(v.w));
        *(uint4*)(As + r * LDW + c) = u;
    }
    __syncthreads();

    const int mw = (wid >> 1) * 32, nw = (wid & 1) * 64;
    float acc[2][8][4];
    gemm_tile(As, Bs, acc, mw, nw, lane);

    const int g = lane >> 2, t2 = (lane & 3) << 1;
    #pragma unroll
    for (int i = 0; i < 2; i++) {
        #pragma unroll
        for (int e2 = 0; e2 < 2; e2++) {
            int rl = mw + 16 * i + g + 8 * e2;
            float ea = eabs_sm[rl];
            float part = 0.0f;
            #pragma unroll
            for (int j = 0; j < 8; j++) {
                #pragma unroll
                for (int e1 = 0; e1 < 2; e1++) {
                    int col = nw + 8 * j + t2 + e1;
                    float q = acc[i][j][e2 * 2 + e1] + s_bq[col];
                    float kv = fmaf(ea, s_Wk[col], s_bk[col]);
                    part += softplus_fast(kv * q);
                }
            }
            part += __shfl_xor_sync(0xffffffffu, part, 1);
            part += __shfl_xor_sync(0xffffffffu, part, 2);
            if ((lane & 3) == 0) atomicAdd(&rowsum[rl], part);
        }
    }
    __syncthreads();

    if (tid < TM) {
        bool head = (tid == 0) || (segs[tid] != segs[tid - 1]);
        if (head && (m0 + tid) < N) {
            int sh = segs[tid];
            float s = 0.0f, c = 0.0f;
            for (int j = tid; j < TM && segs[j] == sh && (m0 + j) < N; j++) {
                s += rowsum[j];
                c += 1.0f;
            }
            atomicAdd(&g_pred[sh], s);
            atomicAdd(&g_cnt[sh], c);
        }
    }
}

// ---------------- pass2: recompute q/embed, 3 chained GEMMs, write out ----------------
__global__ __launch_bounds__(NT, 1)
void pass2_kernel(const float* __restrict__ x, const int* __restrict__ seg,
                  const float* __restrict__ E, const float* __restrict__ bq,
                  const float* __restrict__ Wk, const float* __restrict__ bk,
                  const float* __restrict__ b1, const float* __restrict__ b2,
                  float* __restrict__ out, int N, int B) {
    extern __shared__ uint32_t dyn[];
    uint32_t* As = dyn;
    uint32_t* Bs = dyn + TM * LDW;
    float* Stage = (float*)(dyn + 2 * TM * LDW);   // [128][LDW]
    __shared__ float dval[TM], eabs_sm[TM];
    __shared__ float s_bq[FD], s_Wk[FD], s_bk[FD], s_b1[FD], s_b2[FD];

    const int tid = threadIdx.x, wid = tid >> 5, lane = tid & 31;
    const int m0 = blockIdx.x * TM;

    if (tid < TM) {
        int gr = min(m0 + tid, N - 1);
        int sb = seg[gr]; sb = min(max(sb, 0), B - 1);
        eabs_sm[tid] = fabsf(E[sb]);
        dval[tid] = (E[sb] - g_pred[sb]) / g_cnt[sb] * (1.0f / 128.0f);
        s_bq[tid] = bq[tid]; s_Wk[tid] = Wk[tid]; s_bk[tid] = bk[tid];
        s_b1[tid] = b1[tid]; s_b2[tid] = b2[tid];
    }

    for (int i = tid; i < TM * 32; i += NT) {
        int r = i >> 5, c = (i & 31) << 2;
        *(uint4*)(Bs + r * LDW + c) = ((const uint4*)g_WqT)[i];
        int gr = min(m0 + r, N - 1);
        float4 v = *(const float4*)(x + (size_t)gr * FD + c);
        uint4 u = make_uint4(f2tf32(v.x), f2tf32(v.y), f2tf32(v.z), f2tf32(v.w));
        *(uint4*)(As + r * LDW + c) = u;
    }
    __syncthreads();

    const int mw = (wid >> 1) * 32, nw = (wid & 1) * 64;
    const int g = lane >> 2, t2 = (lane & 3) << 1;
    float acc[2][8][4];

    // GEMM1: q = x @ Wq
    gemm_tile(As, Bs, acc, mw, nw, lane);

    // scale = softplus(kv*q) + dval   (in registers)
    #pragma unroll
    for (int i = 0; i < 2; i++)
        #pragma unroll
        for (int j = 0; j < 8; j++)
            #pragma unroll
            for (int e = 0; e < 4; e++) {
                int rl = mw + 16 * i + g + ((e >> 1) << 3);
                int col = nw + 8 * j + t2 + (e & 1);
                float q = acc[i][j][e] + s_bq[col];
                float kv = fmaf(eabs_sm[rl], s_Wk[col], s_bk[col]);
                acc[i][j][e] = softplus_fast(kv * q) + dval[rl];
            }
    __syncthreads();   // all warps done reading As/Bs for GEMM1

    // Stage = scale ; As = rna(silu(scale)) ; Bs = W1T
    #pragma unroll
    for (int i = 0; i < 2; i++)
        #pragma unroll
        for (int j = 0; j < 8; j++)
            #pragma unroll
            for (int e = 0; e < 4; e++) {
                int rl = mw + 16 * i + g + ((e >> 1) << 3);
                int col = nw + 8 * j + t2 + (e & 1);
                float sc = acc[i][j][e];
                Stage[rl * LDW + col] = sc;
                As[rl * LDW + col] = f2tf32(silu_fast(sc));
            }
    for (int i = tid; i < TM * 32; i += NT) {
        int r = i >> 5, c = (i & 31) << 2;
        *(uint4*)(Bs + r * LDW + c) = ((const uint4*)g_W1T)[i];
    }
    __syncthreads();

    // GEMM2: h1 = silu(scale) @ W1
    gemm_tile(As, Bs, acc, mw, nw, lane);

    // h = silu(h1 + b1) in registers
    #pragma unroll
    for (int i = 0; i < 2; i++)
        #pragma unroll
        for (int j = 0; j < 8; j++)
            #pragma unroll
            for (int e = 0; e < 4; e++) {
                int col = nw + 8 * j + t2 + (e & 1);
                acc[i][j][e] = silu_fast(acc[i][j][e] + s_b1[col]);
            }
    __syncthreads();   // all warps done reading As/Bs for GEMM2

    #pragma unroll
    for (int i = 0; i < 2; i++)
        #pragma unroll
        for (int j = 0; j < 8; j++)
            #pragma unroll
            for (int e = 0; e < 4; e++) {
                int rl = mw + 16 * i + g + ((e >> 1) << 3);
                int col = nw + 8 * j + t2 + (e & 1);
                As[rl * LDW + col] = f2tf32(acc[i][j][e]);
            }
    for (int i = tid; i < TM * 32; i += NT) {
        int r = i >> 5, c = (i & 31) << 2;
        *(uint4*)(Bs + r * LDW + c) = ((const uint4*)g_W2T)[i];
    }
    __syncthreads();

    // GEMM3: h2 = h @ W2 ; out = scale + h2 + b2
    gemm_tile(As, Bs, acc, mw, nw, lane);

    #pragma unroll
    for (int i = 0; i < 2; i++)
        #pragma unroll
        for (int j = 0; j < 8; j++)
            #pragma unroll
            for (int e = 0; e < 4; e++) {
                int rl = mw + 16 * i + g + ((e >> 1) << 3);
                int col = nw + 8 * j + t2 + (e & 1);
                Stage[rl * LDW + col] += acc[i][j][e] + s_b2[col];
            }
    __syncthreads();

    for (int i = tid; i < TM * 32; i += NT) {
        int idx = i << 2;
        int r = idx >> 7, c = idx & 127;
        int gr = m0 + r;
        if (gr < N)
            *(float4*)(out + (size_t)gr * FD + c) = *(float4*)(Stage + r * LDW + c);
    }
}

// ---------------------------------------------------------------------------
extern "C" void kernel_launch(void* const* d_in, const int* in_sizes, int n_in,
                              void* d_out, int out_size) {
    const float* x   = (const float*)d_in[0];
    const float* E   = (const float*)d_in[1];
    const int*   seg = (const int*)d_in[3];
    const float* Wq  = (const float*)d_in[4];
    const float* bq  = (const float*)d_in[5];
    const float* Wk  = (const float*)d_in[6];
    const float* bk  = (const float*)d_in[7];
    const float* W1  = (const float*)d_in[8];
    const float* b1  = (const float*)d_in[9];
    const float* W2  = (const float*)d_in[10];
    const float* b2  = (const float*)d_in[11];
    float* out = (float*)d_out;

    const int N = in_sizes[0] / FD;
    const int B = in_sizes[1];

    const int smem1 = 2 * TM * LDW * 4;   // 135168
    const int smem2 = 3 * TM * LDW * 4;   // 202752
    cudaFuncSetAttribute(pass1_kernel, cudaFuncAttributeMaxDynamicSharedMemorySize, smem1);
    cudaFuncSetAttribute(pass2_kernel, cudaFuncAttributeMaxDynamicSharedMemorySize, smem2);

    prep_kernel<<<(FD * FD + 255) / 256, 256>>>(Wq, W1, W2, B);

    const int nblk = (N + TM - 1) / TM;
    pass1_kernel<<<nblk, NT, smem1>>>(x, seg, E, bq, Wk, bk, N, B);
    pass2_kernel<<<nblk, NT, smem2>>>(x, seg, E, bq, Wk, bk, b1, b2, out, N, B);
}

// round 5
// speedup vs baseline: 1.7014x; 1.0282x over previous
#include <cuda_runtime.h>
#include <cstdint>

#define FD 128
#define TM 128            // rows per CTA
#define NT 256            // 8 warps: 4 row-groups x 2 col-groups
#define LDW 132           // smem row stride (words), conflict-free

// ---------------- device scratch ----------------
__device__ float g_pred[4096];
__device__ float g_cnt[4096];
__device__ uint32_t g_WqT[FD * FD];  // [n][k] transposed, tf32-RN bits
__device__ uint32_t g_W1T[FD * FD];
__device__ uint32_t g_W2T[FD * FD];

// ---------------- helpers ----------------
__device__ __forceinline__ uint32_t f2tf32(float f) {
    uint32_t r;
    asm("cvt.rna.tf32.f32 %0, %1;" : "=r"(r) : "f"(f));
    return r;
}
__device__ __forceinline__ float softplus_fast(float t) {
    return fmaxf(t, 0.0f) + __logf(1.0f + __expf(-fabsf(t)));
}
__device__ __forceinline__ float silu_fast(float v) {
    return __fdividef(v, 1.0f + __expf(-v));
}
__device__ __forceinline__ void mma8(float& c0, float& c1, float& c2, float& c3,
                                     uint32_t a0, uint32_t a1, uint32_t a2, uint32_t a3,
                                     uint32_t b0, uint32_t b1) {
    asm volatile("mma.sync.aligned.m16n8k8.row.col.f32.tf32.tf32.f32 "
                 "{%0,%1,%2,%3}, {%4,%5,%6,%7}, {%8,%9}, {%0,%1,%2,%3};"
                 : "+f"(c0), "+f"(c1), "+f"(c2), "+f"(c3)
                 : "r"(a0), "r"(a1), "r"(a2), "r"(a3), "r"(b0), "r"(b1));
}

// 128x128x128 GEMM tile, software-pipelined k-loop.
// As[m][k], Bs[n][k] at stride LDW (tf32 bits). Warp tile 32x64.
__device__ __forceinline__ void gemm_tile(const uint32_t* __restrict__ As,
                                          const uint32_t* __restrict__ Bs,
                                          float acc[2][8][4], int mw, int nw, int lane) {
    #pragma unroll
    for (int i = 0; i < 2; i++)
        #pragma unroll
        for (int j = 0; j < 8; j++)
            #pragma unroll
            for (int e = 0; e < 4; e++) acc[i][j][e] = 0.0f;

    const int g = lane >> 2, t = lane & 3;
    const uint32_t* a0p = As + (mw + g) * LDW + t;          // row mw+g
    const uint32_t* a1p = As + (mw + 8 + g) * LDW + t;      // row mw+8+g
    const uint32_t* a2p = As + (mw + 16 + g) * LDW + t;
    const uint32_t* a3p = As + (mw + 24 + g) * LDW + t;
    const uint32_t* bp  = Bs + (nw + g) * LDW + t;

    uint32_t a_cur[2][4], b_cur[8][2];
    uint32_t a_nxt[2][4], b_nxt[8][2];

    // prologue: load ks=0
    a_cur[0][0] = a0p[0]; a_cur[0][1] = a1p[0]; a_cur[0][2] = a0p[4]; a_cur[0][3] = a1p[4];
    a_cur[1][0] = a2p[0]; a_cur[1][1] = a3p[0]; a_cur[1][2] = a2p[4]; a_cur[1][3] = a3p[4];
    #pragma unroll
    for (int j = 0; j < 8; j++) {
        b_cur[j][0] = bp[j * 8 * LDW];
        b_cur[j][1] = bp[j * 8 * LDW + 4];
    }

    #pragma unroll
    for (int ks = 0; ks < 16; ks++) {
        if (ks < 15) {
            const int k0 = (ks + 1) * 8;
            a_nxt[0][0] = a0p[k0]; a_nxt[0][1] = a1p[k0];
            a_nxt[0][2] = a0p[k0 + 4]; a_nxt[0][3] = a1p[k0 + 4];
            a_nxt[1][0] = a2p[k0]; a_nxt[1][1] = a3p[k0];
            a_nxt[1][2] = a2p[k0 + 4]; a_nxt[1][3] = a3p[k0 + 4];
            #pragma unroll
            for (int j = 0; j < 8; j++) {
                b_nxt[j][0] = bp[j * 8 * LDW + k0];
                b_nxt[j][1] = bp[j * 8 * LDW + k0 + 4];
            }
        }
        #pragma unroll
        for (int j = 0; j < 8; j++) {
            mma8(acc[0][j][0], acc[0][j][1], acc[0][j][2], acc[0][j][3],
                 a_cur[0][0], a_cur[0][1], a_cur[0][2], a_cur[0][3],
                 b_cur[j][0], b_cur[j][1]);
            mma8(acc[1][j][0], acc[1][j][1], acc[1][j][2], acc[1][j][3],
                 a_cur[1][0], a_cur[1][1], a_cur[1][2], a_cur[1][3],
                 b_cur[j][0], b_cur[j][1]);
        }
        if (ks < 15) {
            #pragma unroll
            for (int i = 0; i < 2; i++)
                #pragma unroll
                for (int e = 0; e < 4; e++) a_cur[i][e] = a_nxt[i][e];
            #pragma unroll
            for (int j = 0; j < 8; j++) {
                b_cur[j][0] = b_nxt[j][0];
                b_cur[j][1] = b_nxt[j][1];
            }
        }
    }
}

// ---------------- prep ----------------
__global__ void prep_kernel(const float* __restrict__ Wq, const float* __restrict__ W1,
                            const float* __restrict__ W2, int B) {
    int i = blockIdx.x * blockDim.x + threadIdx.x;
    if (i < FD * FD) {
        int k = i >> 7, n = i & 127;          // W[k][n] -> WT[n][k]
        g_WqT[n * FD + k] = f2tf32(Wq[i]);
        g_W1T[n * FD + k] = f2tf32(W1[i]);
        g_W2T[n * FD + k] = f2tf32(W2[i]);
    }
    if (i < B) { g_pred[i] = 0.0f; g_cnt[i] = 0.0f; }
}

// ---------------- pass1: GEMM q + softplus + segment sums ----------------
__global__ __launch_bounds__(NT, 1)
void pass1_kernel(const float* __restrict__ x, const int* __restrict__ seg,
                  const float* __restrict__ E, const float* __restrict__ bq,
                  const float* __restrict__ Wk, const float* __restrict__ bk,
                  int N, int B) {
    extern __shared__ uint32_t dyn[];
    uint32_t* As = dyn;
    uint32_t* Bs = dyn + TM * LDW;
    __shared__ float rowsum[TM], eabs_sm[TM];
    __shared__ int segs[TM];
    __shared__ float s_bq[FD], s_Wk[FD], s_bk[FD];

    const int tid = threadIdx.x, wid = tid >> 5, lane = tid & 31;
    const int m0 = blockIdx.x * TM;

    if (tid < TM) {
        int gr = min(m0 + tid, N - 1);
        int sb = seg[gr]; sb = min(max(sb, 0), B - 1);
        segs[tid] = sb;
        eabs_sm[tid] = fabsf(E[sb]);
        rowsum[tid] = 0.0f;
        s_bq[tid] = bq[tid]; s_Wk[tid] = Wk[tid]; s_bk[tid] = bk[tid];
    }

    for (int i = tid; i < TM * 32; i += NT) {
        int r = i >> 5, c = (i & 31) << 2;
        *(uint4*)(Bs + r * LDW + c) = ((const uint4*)g_WqT)[i];
        int gr = min(m0 + r, N - 1);
        float4 v = *(const float4*)(x + (size_t)gr * FD + c);
        *(uint4*)(As + r * LDW + c) =
            make_uint4(f2tf32(v.x), f2tf32(v.y), f2tf32(v.z), f2tf32(v.w));
    }
    __syncthreads();

    const int mw = (wid >> 1) * 32, nw = (wid & 1) * 64;
    float acc[2][8][4];
    gemm_tile(As, Bs, acc, mw, nw, lane);

    const int g = lane >> 2, t2 = (lane & 3) << 1;
    #pragma unroll
    for (int i = 0; i < 2; i++) {
        #pragma unroll
        for (int e2 = 0; e2 < 2; e2++) {
            int rl = mw + 16 * i + g + 8 * e2;
            float ea = eabs_sm[rl];
            float part = 0.0f;
            #pragma unroll
            for (int j = 0; j < 8; j++) {
                #pragma unroll
                for (int e1 = 0; e1 < 2; e1++) {
                    int col = nw + 8 * j + t2 + e1;
                    float q = acc[i][j][e2 * 2 + e1] + s_bq[col];
                    float kv = fmaf(ea, s_Wk[col], s_bk[col]);
                    part += softplus_fast(kv * q);
                }
            }
            part += __shfl_xor_sync(0xffffffffu, part, 1);
            part += __shfl_xor_sync(0xffffffffu, part, 2);
            if ((lane & 3) == 0) atomicAdd(&rowsum[rl], part);
        }
    }
    __syncthreads();

    if (tid < TM) {
        bool head = (tid == 0) || (segs[tid] != segs[tid - 1]);
        if (head && (m0 + tid) < N) {
            int sh = segs[tid];
            float s = 0.0f, c = 0.0f;
            for (int j = tid; j < TM && segs[j] == sh && (m0 + j) < N; j++) {
                s += rowsum[j];
                c += 1.0f;
            }
            atomicAdd(&g_pred[sh], s);
            atomicAdd(&g_cnt[sh], c);
        }
    }
}

// ---------------- pass2: recompute q/embed, 3 chained GEMMs ----------------
__global__ __launch_bounds__(NT, 1)
void pass2_kernel(const float* __restrict__ x, const int* __restrict__ seg,
                  const float* __restrict__ E, const float* __restrict__ bq,
                  const float* __restrict__ Wk, const float* __restrict__ bk,
                  const float* __restrict__ b1, const float* __restrict__ b2,
                  float* __restrict__ out, int N, int B) {
    extern __shared__ uint32_t dyn[];
    uint32_t* As = dyn;
    uint32_t* Bs = dyn + TM * LDW;
    float* Stage = (float*)(dyn + 2 * TM * LDW);
    __shared__ float dval[TM], eabs_sm[TM];
    __shared__ float s_bq[FD], s_Wk[FD], s_bk[FD], s_b1[FD], s_b2[FD];

    const int tid = threadIdx.x, wid = tid >> 5, lane = tid & 31;
    const int m0 = blockIdx.x * TM;

    if (tid < TM) {
        int gr = min(m0 + tid, N - 1);
        int sb = seg[gr]; sb = min(max(sb, 0), B - 1);
        eabs_sm[tid] = fabsf(E[sb]);
        dval[tid] = (E[sb] - g_pred[sb]) / g_cnt[sb] * (1.0f / 128.0f);
        s_bq[tid] = bq[tid]; s_Wk[tid] = Wk[tid]; s_bk[tid] = bk[tid];
        s_b1[tid] = b1[tid]; s_b2[tid] = b2[tid];
    }

    for (int i = tid; i < TM * 32; i += NT) {
        int r = i >> 5, c = (i & 31) << 2;
        *(uint4*)(Bs + r * LDW + c) = ((const uint4*)g_WqT)[i];
        int gr = min(m0 + r, N - 1);
        float4 v = *(const float4*)(x + (size_t)gr * FD + c);
        *(uint4*)(As + r * LDW + c) =
            make_uint4(f2tf32(v.x), f2tf32(v.y), f2tf32(v.z), f2tf32(v.w));
    }
    __syncthreads();

    const int mw = (wid >> 1) * 32, nw = (wid & 1) * 64;
    const int g = lane >> 2, t2 = (lane & 3) << 1;
    float acc[2][8][4];

    // GEMM1: q = x @ Wq
    gemm_tile(As, Bs, acc, mw, nw, lane);

    #pragma unroll
    for (int i = 0; i < 2; i++)
        #pragma unroll
        for (int j = 0; j < 8; j++)
            #pragma unroll
            for (int e = 0; e < 4; e++) {
                int rl = mw + 16 * i + g + ((e >> 1) << 3);
                int col = nw + 8 * j + t2 + (e & 1);
                float q = acc[i][j][e] + s_bq[col];
                float kv = fmaf(eabs_sm[rl], s_Wk[col], s_bk[col]);
                acc[i][j][e] = softplus_fast(kv * q) + dval[rl];
            }
    __syncthreads();

    #pragma unroll
    for (int i = 0; i < 2; i++)
        #pragma unroll
        for (int j = 0; j < 8; j++)
            #pragma unroll
            for (int e = 0; e < 4; e++) {
                int rl = mw + 16 * i + g + ((e >> 1) << 3);
                int col = nw + 8 * j + t2 + (e & 1);
                float sc = acc[i][j][e];
                Stage[rl * LDW + col] = sc;
                As[rl * LDW + col] = f2tf32(silu_fast(sc));
            }
    for (int i = tid; i < TM * 32; i += NT) {
        int r = i >> 5, c = (i & 31) << 2;
        *(uint4*)(Bs + r * LDW + c) = ((const uint4*)g_W1T)[i];
    }
    __syncthreads();

    // GEMM2: h1 = silu(scale) @ W1
    gemm_tile(As, Bs, acc, mw, nw, lane);

    #pragma unroll
    for (int i = 0; i < 2; i++)
        #pragma unroll
        for (int j = 0; j < 8; j++)
            #pragma unroll
            for (int e = 0; e < 4; e++) {
                int col = nw + 8 * j + t2 + (e & 1);
                acc[i][j][e] = silu_fast(acc[i][j][e] + s_b1[col]);
            }
    __syncthreads();

    #pragma unroll
    for (int i = 0; i < 2; i++)
        #pragma unroll
        for (int j = 0; j < 8; j++)
            #pragma unroll
            for (int e = 0; e < 4; e++) {
                int rl = mw + 16 * i + g + ((e >> 1) << 3);
                int col = nw + 8 * j + t2 + (e & 1);
                As[rl * LDW + col] = f2tf32(acc[i][j][e]);
            }
    for (int i = tid; i < TM * 32; i += NT) {
        int r = i >> 5, c = (i & 31) << 2;
        *(uint4*)(Bs + r * LDW + c) = ((const uint4*)g_W2T)[i];
    }
    __syncthreads();

    // GEMM3: h2 = h @ W2 ; out = scale + h2 + b2
    gemm_tile(As, Bs, acc, mw, nw, lane);

    #pragma unroll
    for (int i = 0; i < 2; i++)
        #pragma unroll
        for (int j = 0; j < 8; j++)
            #pragma unroll
            for (int e = 0; e < 4; e++) {
                int rl = mw + 16 * i + g + ((e >> 1) << 3);
                int col = nw + 8 * j + t2 + (e & 1);
                Stage[rl * LDW + col] += acc[i][j][e] + s_b2[col];
            }
    __syncthreads();

    for (int i = tid; i < TM * 32; i += NT) {
        int idx = i << 2;
        int r = idx >> 7, c = idx & 127;
        int gr = m0 + r;
        if (gr < N)
            *(float4*)(out + (size_t)gr * FD + c) = *(float4*)(Stage + r * LDW + c);
    }
}

// ---------------------------------------------------------------------------
extern "C" void kernel_launch(void* const* d_in, const int* in_sizes, int n_in,
                              void* d_out, int out_size) {
    const float* x   = (const float*)d_in[0];
    const float* E   = (const float*)d_in[1];
    const int*   seg = (const int*)d_in[3];
    const float* Wq  = (const float*)d_in[4];
    const float* bq  = (const float*)d_in[5];
    const float* Wk  = (const float*)d_in[6];
    const float* bk  = (const float*)d_in[7];
    const float* W1  = (const float*)d_in[8];
    const float* b1  = (const float*)d_in[9];
    const float* W2  = (const float*)d_in[10];
    const float* b2  = (const float*)d_in[11];
    float* out = (float*)d_out;

    const int N = in_sizes[0] / FD;
    const int B = in_sizes[1];

    const int smem1 = 2 * TM * LDW * 4;   // 135168
    const int smem2 = 3 * TM * LDW * 4;   // 202752
    cudaFuncSetAttribute(pass1_kernel, cudaFuncAttributeMaxDynamicSharedMemorySize, smem1);
    cudaFuncSetAttribute(pass2_kernel, cudaFuncAttributeMaxDynamicSharedMemorySize, smem2);

    prep_kernel<<<(FD * FD + 255) / 256, 256>>>(Wq, W1, W2, B);

    const int nblk = (N + TM - 1) / TM;
    pass1_kernel<<<nblk, NT, smem1>>>(x, seg, E, bq, Wk, bk, N, B);
    pass2_kernel<<<nblk, NT, smem2>>>(x, seg, E, bq, Wk, bk, b1, b2, out, N, B);
}

// round 6
// speedup vs baseline: 2.5132x; 1.4772x over previous
#include <cuda_runtime.h>
#include <cuda_fp16.h>
#include <cstdint>

#define FD 128
#define TM 128            // rows per CTA
#define NT 256            // 8 warps: 4 row-groups x 2 col-groups
#define LDH 68            // smem row stride in 32-bit words (64 half2 + 4 pad) -> conflict-free

// ---------------- device scratch ----------------
__device__ float g_pred[4096];
__device__ float g_cnt[4096];
__device__ uint32_t g_WTq[FD * 64];  // [n][k] transposed, half2-packed along k
__device__ uint32_t g_WT1[FD * 64];
__device__ uint32_t g_WT2[FD * 64];

// ---------------- helpers ----------------
__device__ __forceinline__ uint32_t pack_h2(float a, float b) {
    __half2 h = __floats2half2_rn(a, b);
    return *reinterpret_cast<uint32_t*>(&h);
}
__device__ __forceinline__ float softplus_fast(float t) {
    return fmaxf(t, 0.0f) + __logf(1.0f + __expf(-fabsf(t)));
}
__device__ __forceinline__ float silu_fast(float v) {
    return __fdividef(v, 1.0f + __expf(-v));
}
__device__ __forceinline__ void mma16(float* c, const uint32_t* a, uint32_t b0, uint32_t b1) {
    asm volatile("mma.sync.aligned.m16n8k16.row.col.f32.f16.f16.f32 "
                 "{%0,%1,%2,%3}, {%4,%5,%6,%7}, {%8,%9}, {%0,%1,%2,%3};"
                 : "+f"(c[0]), "+f"(c[1]), "+f"(c[2]), "+f"(c[3])
                 : "r"(a[0]), "r"(a[1]), "r"(a[2]), "r"(a[3]), "r"(b0), "r"(b1));
}

// 128x128x128 fp16 GEMM tile. As[m][k], Bs[n][k] half2-packed, word stride LDH.
// Warp tile 32x64. A fragments prefetched one k-step ahead; B one j ahead.
__device__ __forceinline__ void gemm_tile(const uint32_t* __restrict__ As,
                                          const uint32_t* __restrict__ Bs,
                                          float acc[2][8][4], int mw, int nw, int lane) {
    #pragma unroll
    for (int i = 0; i < 2; i++)
        #pragma unroll
        for (int j = 0; j < 8; j++)
            #pragma unroll
            for (int e = 0; e < 4; e++) acc[i][j][e] = 0.0f;

    const int g = lane >> 2, t = lane & 3;
    const uint32_t* a0p = As + (mw + g) * LDH + t;
    const uint32_t* a1p = a0p + 8 * LDH;
    const uint32_t* a2p = a0p + 16 * LDH;
    const uint32_t* a3p = a0p + 24 * LDH;
    const uint32_t* bp  = Bs + (nw + g) * LDH + t;

    uint32_t a_cur[2][4], a_nxt[2][4];
    a_cur[0][0] = a0p[0]; a_cur[0][1] = a1p[0]; a_cur[0][2] = a0p[4]; a_cur[0][3] = a1p[4];
    a_cur[1][0] = a2p[0]; a_cur[1][1] = a3p[0]; a_cur[1][2] = a2p[4]; a_cur[1][3] = a3p[4];

    #pragma unroll
    for (int ks = 0; ks < 8; ks++) {
        const int kb = ks * 8;
        if (ks < 7) {
            const int k0 = kb + 8;
            a_nxt[0][0] = a0p[k0]; a_nxt[0][1] = a1p[k0];
            a_nxt[0][2] = a0p[k0 + 4]; a_nxt[0][3] = a1p[k0 + 4];
            a_nxt[1][0] = a2p[k0]; a_nxt[1][1] = a3p[k0];
            a_nxt[1][2] = a2p[k0 + 4]; a_nxt[1][3] = a3p[k0 + 4];
        }
        uint32_t b0c = bp[kb], b1c = bp[kb + 4];
        #pragma unroll
        for (int j = 0; j < 8; j++) {
            uint32_t b0n, b1n;
            if (j < 7) {
                b0n = bp[(j + 1) * 8 * LDH + kb];
                b1n = bp[(j + 1) * 8 * LDH + kb + 4];
            }
            mma16(acc[0][j], a_cur[0], b0c, b1c);
            mma16(acc[1][j], a_cur[1], b0c, b1c);
            b0c = b0n; b1c = b1n;
        }
        if (ks < 7) {
            #pragma unroll
            for (int i = 0; i < 2; i++)
                #pragma unroll
                for (int e = 0; e < 4; e++) a_cur[i][e] = a_nxt[i][e];
        }
    }
}

// ---------------- prep: transpose + fp16-pack weights ----------------
__global__ void prep_kernel(const float* __restrict__ Wq, const float* __restrict__ W1,
                            const float* __restrict__ W2) {
    int i = blockIdx.x * blockDim.x + threadIdx.x;   // i over 128*64 half2 words
    if (i < FD * 64) {
        int n = i >> 6, kw = i & 63;
        int k0 = kw * 2;
        g_WTq[i] = pack_h2(Wq[k0 * FD + n], Wq[(k0 + 1) * FD + n]);
        g_WT1[i] = pack_h2(W1[k0 * FD + n], W1[(k0 + 1) * FD + n]);
        g_WT2[i] = pack_h2(W2[k0 * FD + n], W2[(k0 + 1) * FD + n]);
    }
}

// ---------------- tail: zero accumulators for next call ----------------
__global__ void ztail_kernel(int B) {
    int i = blockIdx.x * blockDim.x + threadIdx.x;
    if (i < B) { g_pred[i] = 0.0f; g_cnt[i] = 0.0f; }
}

// shared loaders
__device__ __forceinline__ void load_weight(uint32_t* Bs, const uint32_t* gw, int tid) {
    #pragma unroll 2
    for (int i = tid; i < FD * 16; i += NT) {
        int n = i >> 4, q = i & 15;
        *(uint4*)(Bs + n * LDH + q * 4) = ((const uint4*)gw)[i];
    }
}

// ---------------- pass1: GEMM q + softplus + segment sums ----------------
__global__ __launch_bounds__(NT, 2)
void pass1_kernel(const float* __restrict__ x, const int* __restrict__ seg,
                  const float* __restrict__ E, const float* __restrict__ bq,
                  const float* __restrict__ Wk, const float* __restrict__ bk,
                  int N, int B) {
    extern __shared__ uint32_t dyn[];
    uint32_t* As = dyn;                 // [128][LDH] half2 words
    uint32_t* Bs = dyn + TM * LDH;
    __shared__ float rowsum[TM], eabs_sm[TM];
    __shared__ int segs[TM];
    __shared__ float s_bq[FD], s_Wk[FD], s_bk[FD];

    const int tid = threadIdx.x, wid = tid >> 5, lane = tid & 31;
    const int m0 = blockIdx.x * TM;

    if (tid < TM) {
        int gr = min(m0 + tid, N - 1);
        int sb = seg[gr]; sb = min(max(sb, 0), B - 1);
        segs[tid] = sb;
        eabs_sm[tid] = fabsf(E[sb]);
        rowsum[tid] = 0.0f;
        s_bq[tid] = bq[tid]; s_Wk[tid] = Wk[tid]; s_bk[tid] = bk[tid];
    }

    load_weight(Bs, g_WTq, tid);
    for (int i = tid; i < TM * 32; i += NT) {
        int r = i >> 5, c = (i & 31) << 2;        // c in floats
        int gr = min(m0 + r, N - 1);
        float4 v = *(const float4*)(x + (size_t)gr * FD + c);
        uint2 u = make_uint2(pack_h2(v.x, v.y), pack_h2(v.z, v.w));
        *(uint2*)(As + r * LDH + (c >> 1)) = u;
    }
    __syncthreads();

    const int mw = (wid >> 1) * 32, nw = (wid & 1) * 64;
    float acc[2][8][4];
    gemm_tile(As, Bs, acc, mw, nw, lane);

    const int g = lane >> 2, t2 = (lane & 3) << 1;
    #pragma unroll
    for (int i = 0; i < 2; i++) {
        #pragma unroll
        for (int e2 = 0; e2 < 2; e2++) {
            int rl = mw + 16 * i + g + 8 * e2;
            float ea = eabs_sm[rl];
            float part = 0.0f;
            #pragma unroll
            for (int j = 0; j < 8; j++) {
                #pragma unroll
                for (int e1 = 0; e1 < 2; e1++) {
                    int col = nw + 8 * j + t2 + e1;
                    float q = acc[i][j][e2 * 2 + e1] + s_bq[col];
                    float kv = fmaf(ea, s_Wk[col], s_bk[col]);
                    part += softplus_fast(kv * q);
                }
            }
            part += __shfl_xor_sync(0xffffffffu, part, 1);
            part += __shfl_xor_sync(0xffffffffu, part, 2);
            if ((lane & 3) == 0) atomicAdd(&rowsum[rl], part);
        }
    }
    __syncthreads();

    if (tid < TM) {
        bool head = (tid == 0) || (segs[tid] != segs[tid - 1]);
        if (head && (m0 + tid) < N) {
            int sh = segs[tid];
            float s = 0.0f, c = 0.0f;
            for (int j = tid; j < TM && segs[j] == sh && (m0 + j) < N; j++) {
                s += rowsum[j];
                c += 1.0f;
            }
            atomicAdd(&g_pred[sh], s);
            atomicAdd(&g_cnt[sh], c);
        }
    }
}

// ---------------- pass2: recompute q/embed, 3 chained GEMMs ----------------
__global__ __launch_bounds__(NT, 1)
void pass2_kernel(const float* __restrict__ x, const int* __restrict__ seg,
                  const float* __restrict__ E, const float* __restrict__ bq,
                  const float* __restrict__ Wk, const float* __restrict__ bk,
                  const float* __restrict__ b1, const float* __restrict__ b2,
                  float* __restrict__ out, int N, int B) {
    extern __shared__ uint32_t dyn[];
    uint32_t* As = dyn;
    uint32_t* Bs = dyn + TM * LDH;
    float* Stage = (float*)(dyn + 2 * TM * LDH);   // [128][132] floats
    __shared__ float dval[TM], eabs_sm[TM];
    __shared__ float s_bq[FD], s_Wk[FD], s_bk[FD], s_b1[FD], s_b2[FD];

    const int tid = threadIdx.x, wid = tid >> 5, lane = tid & 31;
    const int m0 = blockIdx.x * TM;

    if (tid < TM) {
        int gr = min(m0 + tid, N - 1);
        int sb = seg[gr]; sb = min(max(sb, 0), B - 1);
        eabs_sm[tid] = fabsf(E[sb]);
        dval[tid] = (E[sb] - g_pred[sb]) / g_cnt[sb] * (1.0f / 128.0f);
        s_bq[tid] = bq[tid]; s_Wk[tid] = Wk[tid]; s_bk[tid] = bk[tid];
        s_b1[tid] = b1[tid]; s_b2[tid] = b2[tid];
    }

    load_weight(Bs, g_WTq, tid);
    for (int i = tid; i < TM * 32; i += NT) {
        int r = i >> 5, c = (i & 31) << 2;
        int gr = min(m0 + r, N - 1);
        float4 v = *(const float4*)(x + (size_t)gr * FD + c);
        uint2 u = make_uint2(pack_h2(v.x, v.y), pack_h2(v.z, v.w));
        *(uint2*)(As + r * LDH + (c >> 1)) = u;
    }
    __syncthreads();

    const int mw = (wid >> 1) * 32, nw = (wid & 1) * 64;
    const int g = lane >> 2, t2 = (lane & 3) << 1;
    float acc[2][8][4];

    // GEMM1: q = x @ Wq
    gemm_tile(As, Bs, acc, mw, nw, lane);

    #pragma unroll
    for (int i = 0; i < 2; i++)
        #pragma unroll
        for (int j = 0; j < 8; j++)
            #pragma unroll
            for (int e = 0; e < 4; e++) {
                int rl = mw + 16 * i + g + ((e >> 1) << 3);
                int col = nw + 8 * j + t2 + (e & 1);
                float q = acc[i][j][e] + s_bq[col];
                float kv = fmaf(eabs_sm[rl], s_Wk[col], s_bk[col]);
                acc[i][j][e] = softplus_fast(kv * q) + dval[rl];
            }
    __syncthreads();

    // Stage = scale ; As = half(silu(scale)) ; Bs = W1T
    #pragma unroll
    for (int i = 0; i < 2; i++)
        #pragma unroll
        for (int j = 0; j < 8; j++)
            #pragma unroll
            for (int e2 = 0; e2 < 2; e2++) {
                int rl = mw + 16 * i + g + 8 * e2;
                int col = nw + 8 * j + t2;
                float s0 = acc[i][j][e2 * 2], s1 = acc[i][j][e2 * 2 + 1];
                Stage[rl * 132 + col] = s0;
                Stage[rl * 132 + col + 1] = s1;
                As[rl * LDH + (col >> 1)] = pack_h2(silu_fast(s0), silu_fast(s1));
            }
    load_weight(Bs, g_WT1, tid);
    __syncthreads();

    // GEMM2: h1 = silu(scale) @ W1
    gemm_tile(As, Bs, acc, mw, nw, lane);

    #pragma unroll
    for (int i = 0; i < 2; i++)
        #pragma unroll
        for (int j = 0; j < 8; j++)
            #pragma unroll
            for (int e = 0; e < 4; e++) {
                int col = nw + 8 * j + t2 + (e & 1);
                acc[i][j][e] = silu_fast(acc[i][j][e] + s_b1[col]);
            }
    __syncthreads();

    #pragma unroll
    for (int i = 0; i < 2; i++)
        #pragma unroll
        for (int j = 0; j < 8; j++)
            #pragma unroll
            for (int e2 = 0; e2 < 2; e2++) {
                int rl = mw + 16 * i + g + 8 * e2;
                int col = nw + 8 * j + t2;
                As[rl * LDH + (col >> 1)] = pack_h2(acc[i][j][e2 * 2], acc[i][j][e2 * 2 + 1]);
            }
    load_weight(Bs, g_WT2, tid);
    __syncthreads();

    // GEMM3: h2 = h @ W2 ; out = scale + h2 + b2
    gemm_tile(As, Bs, acc, mw, nw, lane);

    #pragma unroll
    for (int i = 0; i < 2; i++)
        #pragma unroll
        for (int j = 0; j < 8; j++)
            #pragma unroll
            for (int e = 0; e < 4; e++) {
                int rl = mw + 16 * i + g + ((e >> 1) << 3);
                int col = nw + 8 * j + t2 + (e & 1);
                Stage[rl * 132 + col] += acc[i][j][e] + s_b2[col];
            }
    __syncthreads();

    for (int i = tid; i < TM * 32; i += NT) {
        int idx = i << 2;
        int r = idx >> 7, c = idx & 127;
        int gr = m0 + r;
        if (gr < N)
            *(float4*)(out + (size_t)gr * FD + c) = *(float4*)(Stage + r * 132 + c);
    }
}

// ---------------------------------------------------------------------------
extern "C" void kernel_launch(void* const* d_in, const int* in_sizes, int n_in,
                              void* d_out, int out_size) {
    const float* x   = (const float*)d_in[0];
    const float* E   = (const float*)d_in[1];
    const int*   seg = (const int*)d_in[3];
    const float* Wq  = (const float*)d_in[4];
    const float* bq  = (const float*)d_in[5];
    const float* Wk  = (const float*)d_in[6];
    const float* bk  = (const float*)d_in[7];
    const float* W1  = (const float*)d_in[8];
    const float* b1  = (const float*)d_in[9];
    const float* W2  = (const float*)d_in[10];
    const float* b2  = (const float*)d_in[11];
    float* out = (float*)d_out;

    const int N = in_sizes[0] / FD;
    const int B = in_sizes[1];

    const int smem1 = 2 * TM * LDH * 4;                   // 69632
    const int smem2 = (2 * TM * LDH + TM * 132) * 4;      // 137216
    cudaFuncSetAttribute(pass1_kernel, cudaFuncAttributeMaxDynamicSharedMemorySize, smem1);
    cudaFuncSetAttribute(pass2_kernel, cudaFuncAttributeMaxDynamicSharedMemorySize, smem2);

    prep_kernel<<<(FD * 64 + 255) / 256, 256>>>(Wq, W1, W2);

    const int nblk = (N + TM - 1) / TM;
    pass1_kernel<<<nblk, NT, smem1>>>(x, seg, E, bq, Wk, bk, N, B);
    pass2_kernel<<<nblk, NT, smem2>>>(x, seg, E, bq, Wk, bk, b1, b2, out, N, B);

    ztail_kernel<<<(B + 255) / 256, 256>>>(B);   // zero accumulators for next call
}

// round 7
// speedup vs baseline: 3.5557x; 1.4148x over previous
#include <cuda_runtime.h>
#include <cuda_fp16.h>
#include <cstdint>

#define FD 128
#define TM 128
#define NT 256             // pass1: 8 warps (4x2 tiles of 32x64)
#define NT2 512            // pass2: 16 warps (4x4 tiles of 32x32)
#define LDH 68             // smem row stride in words (64 half2 + 4 pad)

// ---------------- device scratch ----------------
__device__ float g_pred[4096];
__device__ float g_cnt[4096];
__device__ uint32_t g_WTq[FD * 64];       // [n][k] transposed, half2-packed
__device__ uint32_t g_WT1[FD * 64];
__device__ uint32_t g_WT2[FD * 64];
__device__ uint32_t g_embedh[500224 * 64]; // embed as half2 words

// ---------------- helpers ----------------
__device__ __forceinline__ uint32_t pack_h2(float a, float b) {
    __half2 h = __floats2half2_rn(a, b);
    return *reinterpret_cast<uint32_t*>(&h);
}
__device__ __forceinline__ float2 unpack_h2(uint32_t u) {
    __half2 h = *reinterpret_cast<__half2*>(&u);
    return __half22float2(h);
}
__device__ __forceinline__ float softplus_fast(float t) {
    return fmaxf(t, 0.0f) + __logf(1.0f + __expf(-fabsf(t)));
}
__device__ __forceinline__ float silu_fast(float v) {
    return __fdividef(v, 1.0f + __expf(-v));
}
__device__ __forceinline__ void mma16(float* c, const uint32_t* a, uint32_t b0, uint32_t b1) {
    asm volatile("mma.sync.aligned.m16n8k16.row.col.f32.f16.f16.f32 "
                 "{%0,%1,%2,%3}, {%4,%5,%6,%7}, {%8,%9}, {%0,%1,%2,%3};"
                 : "+f"(c[0]), "+f"(c[1]), "+f"(c[2]), "+f"(c[3])
                 : "r"(a[0]), "r"(a[1]), "r"(a[2]), "r"(a[3]), "r"(b0), "r"(b1));
}

// 128x128x128 tile, warp tile 32x64 (pass1)
__device__ __forceinline__ void gemm_tile64(const uint32_t* __restrict__ As,
                                            const uint32_t* __restrict__ Bs,
                                            float acc[2][8][4], int mw, int nw, int lane) {
    #pragma unroll
    for (int i = 0; i < 2; i++)
        #pragma unroll
        for (int j = 0; j < 8; j++)
            #pragma unroll
            for (int e = 0; e < 4; e++) acc[i][j][e] = 0.0f;
    const int g = lane >> 2, t = lane & 3;
    const uint32_t* a0p = As + (mw + g) * LDH + t;
    const uint32_t* a1p = a0p + 8 * LDH;
    const uint32_t* a2p = a0p + 16 * LDH;
    const uint32_t* a3p = a0p + 24 * LDH;
    const uint32_t* bp  = Bs + (nw + g) * LDH + t;
    #pragma unroll
    for (int ks = 0; ks < 8; ks++) {
        const int kb = ks * 8;
        uint32_t a[2][4];
        a[0][0] = a0p[kb]; a[0][1] = a1p[kb]; a[0][2] = a0p[kb + 4]; a[0][3] = a1p[kb + 4];
        a[1][0] = a2p[kb]; a[1][1] = a3p[kb]; a[1][2] = a2p[kb + 4]; a[1][3] = a3p[kb + 4];
        #pragma unroll
        for (int j = 0; j < 8; j++) {
            uint32_t b0 = bp[j * 8 * LDH + kb], b1 = bp[j * 8 * LDH + kb + 4];
            mma16(acc[0][j], a[0], b0, b1);
            mma16(acc[1][j], a[1], b0, b1);
        }
    }
}

// 128x128x128 tile, warp tile 32x32 (pass2)
__device__ __forceinline__ void gemm_tile32(const uint32_t* __restrict__ As,
                                            const uint32_t* __restrict__ Bs,
                                            float acc[2][4][4], int mw, int nw, int lane) {
    #pragma unroll
    for (int i = 0; i < 2; i++)
        #pragma unroll
        for (int j = 0; j < 4; j++)
            #pragma unroll
            for (int e = 0; e < 4; e++) acc[i][j][e] = 0.0f;
    const int g = lane >> 2, t = lane & 3;
    const uint32_t* a0p = As + (mw + g) * LDH + t;
    const uint32_t* a1p = a0p + 8 * LDH;
    const uint32_t* a2p = a0p + 16 * LDH;
    const uint32_t* a3p = a0p + 24 * LDH;
    const uint32_t* bp  = Bs + (nw + g) * LDH + t;
    #pragma unroll
    for (int ks = 0; ks < 8; ks++) {
        const int kb = ks * 8;
        uint32_t a[2][4];
        a[0][0] = a0p[kb]; a[0][1] = a1p[kb]; a[0][2] = a0p[kb + 4]; a[0][3] = a1p[kb + 4];
        a[1][0] = a2p[kb]; a[1][1] = a3p[kb]; a[1][2] = a2p[kb + 4]; a[1][3] = a3p[kb + 4];
        #pragma unroll
        for (int j = 0; j < 4; j++) {
            uint32_t b0 = bp[j * 8 * LDH + kb], b1 = bp[j * 8 * LDH + kb + 4];
            mma16(acc[0][j], a[0], b0, b1);
            mma16(acc[1][j], a[1], b0, b1);
        }
    }
}

// ---------------- prep ----------------
__global__ void prep_kernel(const float* __restrict__ Wq, const float* __restrict__ W1,
                            const float* __restrict__ W2) {
    int i = blockIdx.x * blockDim.x + threadIdx.x;
    if (i < FD * 64) {
        int n = i >> 6, kw = i & 63;
        int k0 = kw * 2;
        g_WTq[i] = pack_h2(Wq[k0 * FD + n], Wq[(k0 + 1) * FD + n]);
        g_WT1[i] = pack_h2(W1[k0 * FD + n], W1[(k0 + 1) * FD + n]);
        g_WT2[i] = pack_h2(W2[k0 * FD + n], W2[(k0 + 1) * FD + n]);
    }
}
__global__ void ztail_kernel(int B) {
    int i = blockIdx.x * blockDim.x + threadIdx.x;
    if (i < B) { g_pred[i] = 0.0f; g_cnt[i] = 0.0f; }
}

// ---------------- pass1: GEMM q + softplus -> embed(half) + segment sums ----------------
__global__ __launch_bounds__(NT, 2)
void pass1_kernel(const float* __restrict__ x, const int* __restrict__ seg,
                  const float* __restrict__ E, const float* __restrict__ bq,
                  const float* __restrict__ Wk, const float* __restrict__ bk,
                  int N, int B) {
    extern __shared__ uint32_t dyn[];
    uint32_t* As = dyn;
    uint32_t* Bs = dyn + TM * LDH;
    __shared__ float rowsum[TM], eabs_sm[TM];
    __shared__ int segs[TM];
    __shared__ float s_bq[FD], s_Wk[FD], s_bk[FD];

    const int tid = threadIdx.x, wid = tid >> 5, lane = tid & 31;
    const int m0 = blockIdx.x * TM;

    if (tid < TM) {
        int gr = min(m0 + tid, N - 1);
        int sb = seg[gr]; sb = min(max(sb, 0), B - 1);
        segs[tid] = sb;
        eabs_sm[tid] = fabsf(E[sb]);
        rowsum[tid] = 0.0f;
        s_bq[tid] = bq[tid]; s_Wk[tid] = Wk[tid]; s_bk[tid] = bk[tid];
    }

    #pragma unroll 2
    for (int i = tid; i < FD * 16; i += NT) {
        int n = i >> 4, q = i & 15;
        *(uint4*)(Bs + n * LDH + q * 4) = ((const uint4*)g_WTq)[i];
    }
    for (int i = tid; i < TM * 32; i += NT) {
        int r = i >> 5, c = (i & 31) << 2;
        int gr = min(m0 + r, N - 1);
        float4 v = *(const float4*)(x + (size_t)gr * FD + c);
        *(uint2*)(As + r * LDH + (c >> 1)) = make_uint2(pack_h2(v.x, v.y), pack_h2(v.z, v.w));
    }
    __syncthreads();

    const int mw = (wid >> 1) * 32, nw = (wid & 1) * 64;
    float acc[2][8][4];
    gemm_tile64(As, Bs, acc, mw, nw, lane);

    const int g = lane >> 2, t2 = (lane & 3) << 1;
    uint32_t packed[2][8][2];
    #pragma unroll
    for (int i = 0; i < 2; i++) {
        #pragma unroll
        for (int e2 = 0; e2 < 2; e2++) {
            int rl = mw + 16 * i + g + 8 * e2;
            float ea = eabs_sm[rl];
            float part = 0.0f;
            #pragma unroll
            for (int j = 0; j < 8; j++) {
                int col = nw + 8 * j + t2;
                float q0 = acc[i][j][e2 * 2] + s_bq[col];
                float q1 = acc[i][j][e2 * 2 + 1] + s_bq[col + 1];
                float v0 = softplus_fast(fmaf(ea, s_Wk[col], s_bk[col]) * q0);
                float v1 = softplus_fast(fmaf(ea, s_Wk[col + 1], s_bk[col + 1]) * q1);
                part += v0 + v1;
                packed[i][j][e2] = pack_h2(v0, v1);
            }
            part += __shfl_xor_sync(0xffffffffu, part, 1);
            part += __shfl_xor_sync(0xffffffffu, part, 2);
            if ((lane & 3) == 0) atomicAdd(&rowsum[rl], part);
        }
    }
    __syncthreads();   // done reading As

    // embed (half2) -> As, then coalesced global store
    #pragma unroll
    for (int i = 0; i < 2; i++)
        #pragma unroll
        for (int e2 = 0; e2 < 2; e2++) {
            int rl = mw + 16 * i + g + 8 * e2;
            #pragma unroll
            for (int j = 0; j < 8; j++)
                As[rl * LDH + ((nw + 8 * j + t2) >> 1)] = packed[i][j][e2];
        }
    __syncthreads();

    for (int i = tid; i < TM * 16; i += NT) {
        int r = i >> 4, wq = (i & 15) << 2;
        int gr = m0 + r;
        if (gr < N) {
            uint4 u;
            u.x = As[r * LDH + wq];     u.y = As[r * LDH + wq + 1];
            u.z = As[r * LDH + wq + 2]; u.w = As[r * LDH + wq + 3];
            *(uint4*)(g_embedh + (size_t)gr * 64 + wq) = u;
        }
    }

    if (tid < TM) {
        bool head = (tid == 0) || (segs[tid] != segs[tid - 1]);
        if (head && (m0 + tid) < N) {
            int sh = segs[tid];
            float s = 0.0f, c = 0.0f;
            for (int j = tid; j < TM && segs[j] == sh && (m0 + j) < N; j++) {
                s += rowsum[j];
                c += 1.0f;
            }
            atomicAdd(&g_pred[sh], s);
            atomicAdd(&g_cnt[sh], c);
        }
    }
}

// ---------------- pass2: load embed, 2 chained GEMMs, write out ----------------
__global__ __launch_bounds__(NT2, 1)
void pass2_kernel(const int* __restrict__ seg, const float* __restrict__ E,
                  const float* __restrict__ b1, const float* __restrict__ b2,
                  float* __restrict__ out, int N, int B) {
    extern __shared__ uint32_t dyn[];
    uint32_t* As = dyn;
    uint32_t* Bs = dyn + TM * LDH;
    float* Stage = (float*)(dyn + 2 * TM * LDH);   // [128][132] floats (scale)
    __shared__ float dval[TM];
    __shared__ float s_b1[FD], s_b2[FD];

    const int tid = threadIdx.x, wid = tid >> 5, lane = tid & 31;
    const int m0 = blockIdx.x * TM;

    if (tid < TM) {
        int gr = min(m0 + tid, N - 1);
        int sb = seg[gr]; sb = min(max(sb, 0), B - 1);
        dval[tid] = (E[sb] - g_pred[sb]) / g_cnt[sb] * (1.0f / 128.0f);
        s_b1[tid] = b1[tid]; s_b2[tid] = b2[tid];
    }
    #pragma unroll 2
    for (int i = tid; i < FD * 16; i += NT2) {
        int n = i >> 4, q = i & 15;
        *(uint4*)(Bs + n * LDH + q * 4) = ((const uint4*)g_WT1)[i];
    }
    __syncthreads();   // dval ready

    // load embed, build scale (Stage) and silu(scale) (As)
    for (int i = tid; i < TM * 16; i += NT2) {
        int r = i >> 4, wq = (i & 15) << 2;
        int gr = min(m0 + r, N - 1);
        uint4 u = *(const uint4*)(g_embedh + (size_t)gr * 64 + wq);
        float dd = dval[r];
        uint32_t w[4] = {u.x, u.y, u.z, u.w};
        #pragma unroll
        for (int q = 0; q < 4; q++) {
            float2 e = unpack_h2(w[q]);
            float s0 = e.x + dd, s1 = e.y + dd;
            Stage[r * 132 + (wq + q) * 2] = s0;
            Stage[r * 132 + (wq + q) * 2 + 1] = s1;
            As[r * LDH + wq + q] = pack_h2(silu_fast(s0), silu_fast(s1));
        }
    }
    __syncthreads();

    const int mw = (wid >> 2) * 32, nw = (wid & 3) * 32;
    const int g = lane >> 2, t2 = (lane & 3) << 1;
    float acc[2][4][4];

    // GEMM2: h1 = silu(scale) @ W1
    gemm_tile32(As, Bs, acc, mw, nw, lane);

    #pragma unroll
    for (int i = 0; i < 2; i++)
        #pragma unroll
        for (int j = 0; j < 4; j++)
            #pragma unroll
            for (int e = 0; e < 4; e++) {
                int col = nw + 8 * j + t2 + (e & 1);
                acc[i][j][e] = silu_fast(acc[i][j][e] + s_b1[col]);
            }
    __syncthreads();   // done reading As/Bs

    #pragma unroll
    for (int i = 0; i < 2; i++)
        #pragma unroll
        for (int e2 = 0; e2 < 2; e2++) {
            int rl = mw + 16 * i + g + 8 * e2;
            #pragma unroll
            for (int j = 0; j < 4; j++)
                As[rl * LDH + ((nw + 8 * j + t2) >> 1)] =
                    pack_h2(acc[i][j][e2 * 2], acc[i][j][e2 * 2 + 1]);
        }
    #pragma unroll 2
    for (int i = tid; i < FD * 16; i += NT2) {
        int n = i >> 4, q = i & 15;
        *(uint4*)(Bs + n * LDH + q * 4) = ((const uint4*)g_WT2)[i];
    }
    __syncthreads();

    // GEMM3: h2 = h @ W2 ; Stage += h2 + b2
    gemm_tile32(As, Bs, acc, mw, nw, lane);

    #pragma unroll
    for (int i = 0; i < 2; i++)
        #pragma unroll
        for (int j = 0; j < 4; j++)
            #pragma unroll
            for (int e = 0; e < 4; e++) {
                int rl = mw + 16 * i + g + ((e >> 1) << 3);
                int col = nw + 8 * j + t2 + (e & 1);
                Stage[rl * 132 + col] += acc[i][j][e] + s_b2[col];
            }
    __syncthreads();

    for (int i = tid; i < TM * 32; i += NT2) {
        int idx = i << 2;
        int r = idx >> 7, c = idx & 127;
        int gr = m0 + r;
        if (gr < N)
            *(float4*)(out + (size_t)gr * FD + c) = *(float4*)(Stage + r * 132 + c);
    }
}

// ---------------------------------------------------------------------------
extern "C" void kernel_launch(void* const* d_in, const int* in_sizes, int n_in,
                              void* d_out, int out_size) {
    const float* x   = (const float*)d_in[0];
    const float* E   = (const float*)d_in[1];
    const int*   seg = (const int*)d_in[3];
    const float* Wq  = (const float*)d_in[4];
    const float* bq  = (const float*)d_in[5];
    const float* Wk  = (const float*)d_in[6];
    const float* bk  = (const float*)d_in[7];
    const float* W1  = (const float*)d_in[8];
    const float* b1  = (const float*)d_in[9];
    const float* W2  = (const float*)d_in[10];
    const float* b2  = (const float*)d_in[11];
    float* out = (float*)d_out;

    const int N = in_sizes[0] / FD;
    const int B = in_sizes[1];

    const int smem1 = 2 * TM * LDH * 4;                   // 69632
    const int smem2 = (2 * TM * LDH + TM * 132) * 4;      // 137216
    cudaFuncSetAttribute(pass1_kernel, cudaFuncAttributeMaxDynamicSharedMemorySize, smem1);
    cudaFuncSetAttribute(pass2_kernel, cudaFuncAttributeMaxDynamicSharedMemorySize, smem2);

    prep_kernel<<<(FD * 64 + 255) / 256, 256>>>(Wq, W1, W2);

    const int nblk = (N + TM - 1) / TM;
    pass1_kernel<<<nblk, NT, smem1>>>(x, seg, E, bq, Wk, bk, N, B);
    pass2_kernel<<<nblk, NT2, smem2>>>(seg, E, b1, b2, out, N, B);

    ztail_kernel<<<(B + 255) / 256, 256>>>(B);
}

// round 8
// speedup vs baseline: 4.1847x; 1.1769x over previous
#include <cuda_runtime.h>
#include <cuda_fp16.h>
#include <cstdint>

#define FD 128
#define TM 128
#define NT 256             // pass1: 8 warps (4x2 tiles of 32x64)
#define NT2 512            // pass2: 16 warps (4x4 tiles of 32x32)
#define LDH 68             // smem row stride in words (64 half2 + 4 pad)

// ---------------- device scratch ----------------
__device__ float g_pred[4096];
__device__ float g_cnt[4096];
__device__ uint32_t g_WTq[FD * 64];        // [n][k] transposed, half2-packed
__device__ uint32_t g_WT1[FD * 64];
__device__ uint32_t g_WT2[FD * 64];
__device__ uint32_t g_embedh[500224 * 64]; // embed as half2 words

// ---------------- helpers ----------------
__device__ __forceinline__ uint32_t pack_h2(float a, float b) {
    __half2 h = __floats2half2_rn(a, b);
    return *reinterpret_cast<uint32_t*>(&h);
}
__device__ __forceinline__ float2 unpack_h2(uint32_t u) {
    __half2 h = *reinterpret_cast<__half2*>(&u);
    return __half22float2(h);
}
__device__ __forceinline__ float softplus_fast(float t) {
    return fmaxf(t, 0.0f) + __logf(1.0f + __expf(-fabsf(t)));
}
__device__ __forceinline__ float silu_fast(float v) {
    return __fdividef(v, 1.0f + __expf(-v));
}
__device__ __forceinline__ void mma16(float* c, const uint32_t* a, uint32_t b0, uint32_t b1) {
    asm volatile("mma.sync.aligned.m16n8k16.row.col.f32.f16.f16.f32 "
                 "{%0,%1,%2,%3}, {%4,%5,%6,%7}, {%8,%9}, {%0,%1,%2,%3};"
                 : "+f"(c[0]), "+f"(c[1]), "+f"(c[2]), "+f"(c[3])
                 : "r"(a[0]), "r"(a[1]), "r"(a[2]), "r"(a[3]), "r"(b0), "r"(b1));
}

// 128x128x128 tile, warp tile 32x64 (pass1)
__device__ __forceinline__ void gemm_tile64(const uint32_t* __restrict__ As,
                                            const uint32_t* __restrict__ Bs,
                                            float acc[2][8][4], int mw, int nw, int lane) {
    #pragma unroll
    for (int i = 0; i < 2; i++)
        #pragma unroll
        for (int j = 0; j < 8; j++)
            #pragma unroll
            for (int e = 0; e < 4; e++) acc[i][j][e] = 0.0f;
    const int g = lane >> 2, t = lane & 3;
    const uint32_t* a0p = As + (mw + g) * LDH + t;
    const uint32_t* a1p = a0p + 8 * LDH;
    const uint32_t* a2p = a0p + 16 * LDH;
    const uint32_t* a3p = a0p + 24 * LDH;
    const uint32_t* bp  = Bs + (nw + g) * LDH + t;
    #pragma unroll
    for (int ks = 0; ks < 8; ks++) {
        const int kb = ks * 8;
        uint32_t a[2][4];
        a[0][0] = a0p[kb]; a[0][1] = a1p[kb]; a[0][2] = a0p[kb + 4]; a[0][3] = a1p[kb + 4];
        a[1][0] = a2p[kb]; a[1][1] = a3p[kb]; a[1][2] = a2p[kb + 4]; a[1][3] = a3p[kb + 4];
        #pragma unroll
        for (int j = 0; j < 8; j++) {
            uint32_t b0 = bp[j * 8 * LDH + kb], b1 = bp[j * 8 * LDH + kb + 4];
            mma16(acc[0][j], a[0], b0, b1);
            mma16(acc[1][j], a[1], b0, b1);
        }
    }
}

// 128x128x128 tile, warp tile 32x32 (pass2)
__device__ __forceinline__ void gemm_tile32(const uint32_t* __restrict__ As,
                                            const uint32_t* __restrict__ Bs,
                                            float acc[2][4][4], int mw, int nw, int lane) {
    #pragma unroll
    for (int i = 0; i < 2; i++)
        #pragma unroll
        for (int j = 0; j < 4; j++)
            #pragma unroll
            for (int e = 0; e < 4; e++) acc[i][j][e] = 0.0f;
    const int g = lane >> 2, t = lane & 3;
    const uint32_t* a0p = As + (mw + g) * LDH + t;
    const uint32_t* a1p = a0p + 8 * LDH;
    const uint32_t* a2p = a0p + 16 * LDH;
    const uint32_t* a3p = a0p + 24 * LDH;
    const uint32_t* bp  = Bs + (nw + g) * LDH + t;
    #pragma unroll
    for (int ks = 0; ks < 8; ks++) {
        const int kb = ks * 8;
        uint32_t a[2][4];
        a[0][0] = a0p[kb]; a[0][1] = a1p[kb]; a[0][2] = a0p[kb + 4]; a[0][3] = a1p[kb + 4];
        a[1][0] = a2p[kb]; a[1][1] = a3p[kb]; a[1][2] = a2p[kb + 4]; a[1][3] = a3p[kb + 4];
        #pragma unroll
        for (int j = 0; j < 4; j++) {
            uint32_t b0 = bp[j * 8 * LDH + kb], b1 = bp[j * 8 * LDH + kb + 4];
            mma16(acc[0][j], a[0], b0, b1);
            mma16(acc[1][j], a[1], b0, b1);
        }
    }
}

// ---------------- prep ----------------
__global__ void prep_kernel(const float* __restrict__ Wq, const float* __restrict__ W1,
                            const float* __restrict__ W2) {
    int i = blockIdx.x * blockDim.x + threadIdx.x;
    if (i < FD * 64) {
        int n = i >> 6, kw = i & 63;
        int k0 = kw * 2;
        g_WTq[i] = pack_h2(Wq[k0 * FD + n], Wq[(k0 + 1) * FD + n]);
        g_WT1[i] = pack_h2(W1[k0 * FD + n], W1[(k0 + 1) * FD + n]);
        g_WT2[i] = pack_h2(W2[k0 * FD + n], W2[(k0 + 1) * FD + n]);
    }
}
__global__ void ztail_kernel(int B) {
    int i = blockIdx.x * blockDim.x + threadIdx.x;
    if (i < B) { g_pred[i] = 0.0f; g_cnt[i] = 0.0f; }
}

// ---------------- pass1: GEMM q + softplus -> embed(half) + segment sums ----------------
__global__ __launch_bounds__(NT, 2)
void pass1_kernel(const float* __restrict__ x, const int* __restrict__ seg,
                  const float* __restrict__ E, const float* __restrict__ bq,
                  const float* __restrict__ Wk, const float* __restrict__ bk,
                  int N, int B) {
    extern __shared__ uint32_t dyn[];
    uint32_t* As = dyn;
    uint32_t* Bs = dyn + TM * LDH;
    __shared__ float rowsum[TM], eabs_sm[TM];
    __shared__ int segs[TM];
    __shared__ float s_bq[FD], s_Wk[FD], s_bk[FD];

    const int tid = threadIdx.x, wid = tid >> 5, lane = tid & 31;
    const int m0 = blockIdx.x * TM;

    if (tid < TM) {
        int gr = min(m0 + tid, N - 1);
        int sb = seg[gr]; sb = min(max(sb, 0), B - 1);
        segs[tid] = sb;
        eabs_sm[tid] = fabsf(E[sb]);
        rowsum[tid] = 0.0f;
        s_bq[tid] = bq[tid]; s_Wk[tid] = Wk[tid]; s_bk[tid] = bk[tid];
    }

    #pragma unroll 2
    for (int i = tid; i < FD * 16; i += NT) {
        int n = i >> 4, q = i & 15;
        *(uint4*)(Bs + n * LDH + q * 4) = ((const uint4*)g_WTq)[i];
    }
    for (int i = tid; i < TM * 32; i += NT) {
        int r = i >> 5, c = (i & 31) << 2;
        int gr = min(m0 + r, N - 1);
        float4 v = *(const float4*)(x + (size_t)gr * FD + c);
        *(uint2*)(As + r * LDH + (c >> 1)) = make_uint2(pack_h2(v.x, v.y), pack_h2(v.z, v.w));
    }
    __syncthreads();

    const int mw = (wid >> 1) * 32, nw = (wid & 1) * 64;
    float acc[2][8][4];
    gemm_tile64(As, Bs, acc, mw, nw, lane);

    const int g = lane >> 2, t2 = (lane & 3) << 1;
    uint32_t packed[2][8][2];
    #pragma unroll
    for (int i = 0; i < 2; i++) {
        #pragma unroll
        for (int e2 = 0; e2 < 2; e2++) {
            int rl = mw + 16 * i + g + 8 * e2;
            float ea = eabs_sm[rl];
            float part = 0.0f;
            #pragma unroll
            for (int j = 0; j < 8; j++) {
                int col = nw + 8 * j + t2;
                float q0 = acc[i][j][e2 * 2] + s_bq[col];
                float q1 = acc[i][j][e2 * 2 + 1] + s_bq[col + 1];
                float v0 = softplus_fast(fmaf(ea, s_Wk[col], s_bk[col]) * q0);
                float v1 = softplus_fast(fmaf(ea, s_Wk[col + 1], s_bk[col + 1]) * q1);
                part += v0 + v1;
                packed[i][j][e2] = pack_h2(v0, v1);
            }
            part += __shfl_xor_sync(0xffffffffu, part, 1);
            part += __shfl_xor_sync(0xffffffffu, part, 2);
            if ((lane & 3) == 0) atomicAdd(&rowsum[rl], part);
        }
    }
    __syncthreads();   // done reading As

    // embed (half2) -> As, then coalesced global store
    #pragma unroll
    for (int i = 0; i < 2; i++)
        #pragma unroll
        for (int e2 = 0; e2 < 2; e2++) {
            int rl = mw + 16 * i + g + 8 * e2;
            #pragma unroll
            for (int j = 0; j < 8; j++)
                As[rl * LDH + ((nw + 8 * j + t2) >> 1)] = packed[i][j][e2];
        }
    __syncthreads();

    for (int i = tid; i < TM * 16; i += NT) {
        int r = i >> 4, wq = (i & 15) << 2;
        int gr = m0 + r;
        if (gr < N) {
            uint4 u;
            u.x = As[r * LDH + wq];     u.y = As[r * LDH + wq + 1];
            u.z = As[r * LDH + wq + 2]; u.w = As[r * LDH + wq + 3];
            *(uint4*)(g_embedh + (size_t)gr * 64 + wq) = u;
        }
    }

    if (tid < TM) {
        bool head = (tid == 0) || (segs[tid] != segs[tid - 1]);
        if (head && (m0 + tid) < N) {
            int sh = segs[tid];
            float s = 0.0f, c = 0.0f;
            for (int j = tid; j < TM && segs[j] == sh && (m0 + j) < N; j++) {
                s += rowsum[j];
                c += 1.0f;
            }
            atomicAdd(&g_pred[sh], s);
            atomicAdd(&g_cnt[sh], c);
        }
    }
}

// ---------------- pass2: load embed, 2 chained GEMMs, direct fragment epilogue ---------
__global__ __launch_bounds__(NT2, 2)
void pass2_kernel(const int* __restrict__ seg, const float* __restrict__ E,
                  const float* __restrict__ b1, const float* __restrict__ b2,
                  float* __restrict__ out, int N, int B) {
    extern __shared__ uint32_t dyn[];
    uint32_t* As = dyn;
    uint32_t* Bs = dyn + TM * LDH;
    __shared__ float dval[TM];
    __shared__ float s_b1[FD], s_b2[FD];

    const int tid = threadIdx.x, wid = tid >> 5, lane = tid & 31;
    const int m0 = blockIdx.x * TM;

    if (tid < TM) {
        int gr = min(m0 + tid, N - 1);
        int sb = seg[gr]; sb = min(max(sb, 0), B - 1);
        dval[tid] = (E[sb] - g_pred[sb]) / g_cnt[sb] * (1.0f / 128.0f);
        s_b1[tid] = b1[tid]; s_b2[tid] = b2[tid];
    }
    #pragma unroll 2
    for (int i = tid; i < FD * 16; i += NT2) {
        int n = i >> 4, q = i & 15;
        *(uint4*)(Bs + n * LDH + q * 4) = ((const uint4*)g_WT1)[i];
    }
    __syncthreads();   // dval ready

    // load embed, build silu(embed + d) -> As
    for (int i = tid; i < TM * 16; i += NT2) {
        int r = i >> 4, wq = (i & 15) << 2;
        int gr = min(m0 + r, N - 1);
        uint4 u = *(const uint4*)(g_embedh + (size_t)gr * 64 + wq);
        float dd = dval[r];
        uint32_t w[4] = {u.x, u.y, u.z, u.w};
        #pragma unroll
        for (int q = 0; q < 4; q++) {
            float2 e = unpack_h2(w[q]);
            As[r * LDH + wq + q] = pack_h2(silu_fast(e.x + dd), silu_fast(e.y + dd));
        }
    }
    __syncthreads();

    const int mw = (wid >> 2) * 32, nw = (wid & 3) * 32;
    const int g = lane >> 2, t2 = (lane & 3) << 1;
    float acc[2][4][4];

    // GEMM2: h1 = silu(scale) @ W1
    gemm_tile32(As, Bs, acc, mw, nw, lane);

    #pragma unroll
    for (int i = 0; i < 2; i++)
        #pragma unroll
        for (int j = 0; j < 4; j++)
            #pragma unroll
            for (int e = 0; e < 4; e++) {
                int col = nw + 8 * j + t2 + (e & 1);
                acc[i][j][e] = silu_fast(acc[i][j][e] + s_b1[col]);
            }
    __syncthreads();   // done reading As/Bs

    #pragma unroll
    for (int i = 0; i < 2; i++)
        #pragma unroll
        for (int e2 = 0; e2 < 2; e2++) {
            int rl = mw + 16 * i + g + 8 * e2;
            #pragma unroll
            for (int j = 0; j < 4; j++)
                As[rl * LDH + ((nw + 8 * j + t2) >> 1)] =
                    pack_h2(acc[i][j][e2 * 2], acc[i][j][e2 * 2 + 1]);
        }
    #pragma unroll 2
    for (int i = tid; i < FD * 16; i += NT2) {
        int n = i >> 4, q = i & 15;
        *(uint4*)(Bs + n * LDH + q * 4) = ((const uint4*)g_WT2)[i];
    }
    __syncthreads();

    // GEMM3: h2 = h @ W2
    gemm_tile32(As, Bs, acc, mw, nw, lane);

    // direct fragment epilogue: out = (embed + d) + h2 + b2
    // embed re-read from g_embedh (L2-hot); float2 stores, 4 lanes = 32B sector
    #pragma unroll
    for (int i = 0; i < 2; i++)
        #pragma unroll
        for (int e2 = 0; e2 < 2; e2++) {
            int rl = mw + 16 * i + g + 8 * e2;
            int gr = m0 + rl;
            if (gr < N) {
                float dd = dval[rl];
                #pragma unroll
                for (int j = 0; j < 4; j++) {
                    int col = nw + 8 * j + t2;
                    float2 e = unpack_h2(g_embedh[(size_t)gr * 64 + (col >> 1)]);
                    float2 o;
                    o.x = e.x + dd + acc[i][j][e2 * 2]     + s_b2[col];
                    o.y = e.y + dd + acc[i][j][e2 * 2 + 1] + s_b2[col + 1];
                    *(float2*)(out + (size_t)gr * FD + col) = o;
                }
            }
        }
}

// ---------------------------------------------------------------------------
extern "C" void kernel_launch(void* const* d_in, const int* in_sizes, int n_in,
                              void* d_out, int out_size) {
    const float* x   = (const float*)d_in[0];
    const float* E   = (const float*)d_in[1];
    const int*   seg = (const int*)d_in[3];
    const float* Wq  = (const float*)d_in[4];
    const float* bq  = (const float*)d_in[5];
    const float* Wk  = (const float*)d_in[6];
    const float* bk  = (const float*)d_in[7];
    const float* W1  = (const float*)d_in[8];
    const float* b1  = (const float*)d_in[9];
    const float* W2  = (const float*)d_in[10];
    const float* b2  = (const float*)d_in[11];
    float* out = (float*)d_out;

    const int N = in_sizes[0] / FD;
    const int B = in_sizes[1];

    const int smem1 = 2 * TM * LDH * 4;   // 69632
    const int smem2 = 2 * TM * LDH * 4;   // 69632
    cudaFuncSetAttribute(pass1_kernel, cudaFuncAttributeMaxDynamicSharedMemorySize, smem1);
    cudaFuncSetAttribute(pass2_kernel, cudaFuncAttributeMaxDynamicSharedMemorySize, smem2);

    prep_kernel<<<(FD * 64 + 255) / 256, 256>>>(Wq, W1, W2);

    const int nblk = (N + TM - 1) / TM;
    pass1_kernel<<<nblk, NT, smem1>>>(x, seg, E, bq, Wk, bk, N, B);
    pass2_kernel<<<nblk, NT2, smem2>>>(seg, E, b1, b2, out, N, B);

    ztail_kernel<<<(B + 255) / 256, 256>>>(B);
}

// round 9
// speedup vs baseline: 4.6891x; 1.1205x over previous
#include <cuda_runtime.h>
#include <cuda_fp16.h>
#include <cstdint>

#define FD 128
#define TM 128
#define NT2 512            // 16 warps (4x4 tiles of 32x32)
#define LDH 68             // smem row stride in words (64 half2 + 4 pad)

// ---------------- device scratch ----------------
__device__ float g_pred[4096];
__device__ float g_cnt[4096];
__device__ uint32_t g_WTq[FD * 64];        // [n][k] transposed, half2-packed
__device__ uint32_t g_WT1[FD * 64];
__device__ uint32_t g_WT2[FD * 64];
__device__ uint32_t g_embedh[500224 * 64]; // embed as half2 words

// ---------------- helpers ----------------
__device__ __forceinline__ uint32_t pack_h2(float a, float b) {
    __half2 h = __floats2half2_rn(a, b);
    return *reinterpret_cast<uint32_t*>(&h);
}
__device__ __forceinline__ float2 unpack_h2(uint32_t u) {
    __half2 h = *reinterpret_cast<__half2*>(&u);
    return __half22float2(h);
}
__device__ __forceinline__ float softplus_fast(float t) {
    return fmaxf(t, 0.0f) + __logf(1.0f + __expf(-fabsf(t)));
}
__device__ __forceinline__ float silu_fast(float v) {
    return __fdividef(v, 1.0f + __expf(-v));
}
__device__ __forceinline__ void mma16(float* c, const uint32_t* a, uint32_t b0, uint32_t b1) {
    asm volatile("mma.sync.aligned.m16n8k16.row.col.f32.f16.f16.f32 "
                 "{%0,%1,%2,%3}, {%4,%5,%6,%7}, {%8,%9}, {%0,%1,%2,%3};"
                 : "+f"(c[0]), "+f"(c[1]), "+f"(c[2]), "+f"(c[3])
                 : "r"(a[0]), "r"(a[1]), "r"(a[2]), "r"(a[3]), "r"(b0), "r"(b1));
}

// 128x128x128 tile, warp tile 32x32
__device__ __forceinline__ void gemm_tile32(const uint32_t* __restrict__ As,
                                            const uint32_t* __restrict__ Bs,
                                            float acc[2][4][4], int mw, int nw, int lane) {
    #pragma unroll
    for (int i = 0; i < 2; i++)
        #pragma unroll
        for (int j = 0; j < 4; j++)
            #pragma unroll
            for (int e = 0; e < 4; e++) acc[i][j][e] = 0.0f;
    const int g = lane >> 2, t = lane & 3;
    const uint32_t* a0p = As + (mw + g) * LDH + t;
    const uint32_t* a1p = a0p + 8 * LDH;
    const uint32_t* a2p = a0p + 16 * LDH;
    const uint32_t* a3p = a0p + 24 * LDH;
    const uint32_t* bp  = Bs + (nw + g) * LDH + t;
    #pragma unroll
    for (int ks = 0; ks < 8; ks++) {
        const int kb = ks * 8;
        uint32_t a[2][4];
        a[0][0] = a0p[kb]; a[0][1] = a1p[kb]; a[0][2] = a0p[kb + 4]; a[0][3] = a1p[kb + 4];
        a[1][0] = a2p[kb]; a[1][1] = a3p[kb]; a[1][2] = a2p[kb + 4]; a[1][3] = a3p[kb + 4];
        #pragma unroll
        for (int j = 0; j < 4; j++) {
            uint32_t b0 = bp[j * 8 * LDH + kb], b1 = bp[j * 8 * LDH + kb + 4];
            mma16(acc[0][j], a[0], b0, b1);
            mma16(acc[1][j], a[1], b0, b1);
        }
    }
}

// ---------------- prep: pack weights + zero accumulators ----------------
__global__ void prep_kernel(const float* __restrict__ Wq, const float* __restrict__ W1,
                            const float* __restrict__ W2, int B) {
    int i = blockIdx.x * blockDim.x + threadIdx.x;
    if (i < FD * 64) {
        int n = i >> 6, kw = i & 63;
        int k0 = kw * 2;
        g_WTq[i] = pack_h2(Wq[k0 * FD + n], Wq[(k0 + 1) * FD + n]);
        g_WT1[i] = pack_h2(W1[k0 * FD + n], W1[(k0 + 1) * FD + n]);
        g_WT2[i] = pack_h2(W2[k0 * FD + n], W2[(k0 + 1) * FD + n]);
    }
    if (i < B) { g_pred[i] = 0.0f; g_cnt[i] = 0.0f; }
}

// ---------------- pass1: GEMM q + softplus -> embed(half, direct) + segment sums -------
__global__ __launch_bounds__(NT2, 2)
void pass1_kernel(const float* __restrict__ x, const int* __restrict__ seg,
                  const float* __restrict__ E, const float* __restrict__ bq,
                  const float* __restrict__ Wk, const float* __restrict__ bk,
                  int N, int B) {
    extern __shared__ uint32_t dyn[];
    uint32_t* As = dyn;
    uint32_t* Bs = dyn + TM * LDH;
    __shared__ float rowsum[TM], eabs_sm[TM];
    __shared__ int segs[TM];
    __shared__ float s_bq[FD], s_Wk[FD], s_bk[FD];

    const int tid = threadIdx.x, wid = tid >> 5, lane = tid & 31;
    const int m0 = blockIdx.x * TM;

    if (tid < TM) {
        int gr = min(m0 + tid, N - 1);
        int sb = seg[gr]; sb = min(max(sb, 0), B - 1);
        segs[tid] = sb;
        eabs_sm[tid] = fabsf(E[sb]);
        rowsum[tid] = 0.0f;
        s_bq[tid] = bq[tid]; s_Wk[tid] = Wk[tid]; s_bk[tid] = bk[tid];
    }

    #pragma unroll 2
    for (int i = tid; i < FD * 16; i += NT2) {
        int n = i >> 4, q = i & 15;
        *(uint4*)(Bs + n * LDH + q * 4) = ((const uint4*)g_WTq)[i];
    }
    for (int i = tid; i < TM * 32; i += NT2) {
        int r = i >> 5, c = (i & 31) << 2;
        int gr = min(m0 + r, N - 1);
        float4 v = *(const float4*)(x + (size_t)gr * FD + c);
        *(uint2*)(As + r * LDH + (c >> 1)) = make_uint2(pack_h2(v.x, v.y), pack_h2(v.z, v.w));
    }
    __syncthreads();

    const int mw = (wid >> 2) * 32, nw = (wid & 3) * 32;
    float acc[2][4][4];
    gemm_tile32(As, Bs, acc, mw, nw, lane);

    // epilogue: softplus + direct embed store + row partial sums
    const int g = lane >> 2, t2 = (lane & 3) << 1;
    #pragma unroll
    for (int i = 0; i < 2; i++) {
        #pragma unroll
        for (int e2 = 0; e2 < 2; e2++) {
            int rl = mw + 16 * i + g + 8 * e2;
            int gr = m0 + rl;
            float ea = eabs_sm[rl];
            float part = 0.0f;
            #pragma unroll
            for (int j = 0; j < 4; j++) {
                int col = nw + 8 * j + t2;
                float q0 = acc[i][j][e2 * 2] + s_bq[col];
                float q1 = acc[i][j][e2 * 2 + 1] + s_bq[col + 1];
                float v0 = softplus_fast(fmaf(ea, s_Wk[col], s_bk[col]) * q0);
                float v1 = softplus_fast(fmaf(ea, s_Wk[col + 1], s_bk[col + 1]) * q1);
                part += v0 + v1;
                if (gr < N)
                    g_embedh[(size_t)gr * 64 + (col >> 1)] = pack_h2(v0, v1);
            }
            part += __shfl_xor_sync(0xffffffffu, part, 1);
            part += __shfl_xor_sync(0xffffffffu, part, 2);
            if ((lane & 3) == 0) atomicAdd(&rowsum[rl], part);
        }
    }
    __syncthreads();

    if (tid < TM) {
        bool head = (tid == 0) || (segs[tid] != segs[tid - 1]);
        if (head && (m0 + tid) < N) {
            int sh = segs[tid];
            float s = 0.0f, c = 0.0f;
            for (int j = tid; j < TM && segs[j] == sh && (m0 + j) < N; j++) {
                s += rowsum[j];
                c += 1.0f;
            }
            atomicAdd(&g_pred[sh], s);
            atomicAdd(&g_cnt[sh], c);
        }
    }
}

// ---------------- pass2: load embed, 2 chained GEMMs, direct fragment epilogue ---------
__global__ __launch_bounds__(NT2, 2)
void pass2_kernel(const int* __restrict__ seg, const float* __restrict__ E,
                  const float* __restrict__ b1, const float* __restrict__ b2,
                  float* __restrict__ out, int N, int B) {
    extern __shared__ uint32_t dyn[];
    uint32_t* As = dyn;
    uint32_t* Bs = dyn + TM * LDH;
    __shared__ float dval[TM];
    __shared__ float s_b1[FD], s_b2[FD];

    const int tid = threadIdx.x, wid = tid >> 5, lane = tid & 31;
    const int m0 = blockIdx.x * TM;

    if (tid < TM) {
        int gr = min(m0 + tid, N - 1);
        int sb = seg[gr]; sb = min(max(sb, 0), B - 1);
        dval[tid] = (E[sb] - g_pred[sb]) / g_cnt[sb] * (1.0f / 128.0f);
        s_b1[tid] = b1[tid]; s_b2[tid] = b2[tid];
    }
    #pragma unroll 2
    for (int i = tid; i < FD * 16; i += NT2) {
        int n = i >> 4, q = i & 15;
        *(uint4*)(Bs + n * LDH + q * 4) = ((const uint4*)g_WT1)[i];
    }
    __syncthreads();   // dval ready

    // load embed, build silu(embed + d) -> As
    for (int i = tid; i < TM * 16; i += NT2) {
        int r = i >> 4, wq = (i & 15) << 2;
        int gr = min(m0 + r, N - 1);
        uint4 u = *(const uint4*)(g_embedh + (size_t)gr * 64 + wq);
        float dd = dval[r];
        uint32_t w[4] = {u.x, u.y, u.z, u.w};
        #pragma unroll
        for (int q = 0; q < 4; q++) {
            float2 e = unpack_h2(w[q]);
            As[r * LDH + wq + q] = pack_h2(silu_fast(e.x + dd), silu_fast(e.y + dd));
        }
    }
    __syncthreads();

    const int mw = (wid >> 2) * 32, nw = (wid & 3) * 32;
    const int g = lane >> 2, t2 = (lane & 3) << 1;
    float acc[2][4][4];

    // GEMM2: h1 = silu(scale) @ W1
    gemm_tile32(As, Bs, acc, mw, nw, lane);

    #pragma unroll
    for (int i = 0; i < 2; i++)
        #pragma unroll
        for (int j = 0; j < 4; j++)
            #pragma unroll
            for (int e = 0; e < 4; e++) {
                int col = nw + 8 * j + t2 + (e & 1);
                acc[i][j][e] = silu_fast(acc[i][j][e] + s_b1[col]);
            }
    __syncthreads();   // done reading As/Bs

    #pragma unroll
    for (int i = 0; i < 2; i++)
        #pragma unroll
        for (int e2 = 0; e2 < 2; e2++) {
            int rl = mw + 16 * i + g + 8 * e2;
            #pragma unroll
            for (int j = 0; j < 4; j++)
                As[rl * LDH + ((nw + 8 * j + t2) >> 1)] =
                    pack_h2(acc[i][j][e2 * 2], acc[i][j][e2 * 2 + 1]);
        }
    #pragma unroll 2
    for (int i = tid; i < FD * 16; i += NT2) {
        int n = i >> 4, q = i & 15;
        *(uint4*)(Bs + n * LDH + q * 4) = ((const uint4*)g_WT2)[i];
    }
    __syncthreads();

    // GEMM3: h2 = h @ W2
    gemm_tile32(As, Bs, acc, mw, nw, lane);

    // direct fragment epilogue: out = (embed + d) + h2 + b2
    #pragma unroll
    for (int i = 0; i < 2; i++)
        #pragma unroll
        for (int e2 = 0; e2 < 2; e2++) {
            int rl = mw + 16 * i + g + 8 * e2;
            int gr = m0 + rl;
            if (gr < N) {
                float dd = dval[rl];
                #pragma unroll
                for (int j = 0; j < 4; j++) {
                    int col = nw + 8 * j + t2;
                    float2 e = unpack_h2(g_embedh[(size_t)gr * 64 + (col >> 1)]);
                    float2 o;
                    o.x = e.x + dd + acc[i][j][e2 * 2]     + s_b2[col];
                    o.y = e.y + dd + acc[i][j][e2 * 2 + 1] + s_b2[col + 1];
                    *(float2*)(out + (size_t)gr * FD + col) = o;
                }
            }
        }
}

// ---------------------------------------------------------------------------
extern "C" void kernel_launch(void* const* d_in, const int* in_sizes, int n_in,
                              void* d_out, int out_size) {
    const float* x   = (const float*)d_in[0];
    const float* E   = (const float*)d_in[1];
    const int*   seg = (const int*)d_in[3];
    const float* Wq  = (const float*)d_in[4];
    const float* bq  = (const float*)d_in[5];
    const float* Wk  = (const float*)d_in[6];
    const float* bk  = (const float*)d_in[7];
    const float* W1  = (const float*)d_in[8];
    const float* b1  = (const float*)d_in[9];
    const float* W2  = (const float*)d_in[10];
    const float* b2  = (const float*)d_in[11];
    float* out = (float*)d_out;

    const int N = in_sizes[0] / FD;
    const int B = in_sizes[1];

    const int smem = 2 * TM * LDH * 4;   // 69632
    cudaFuncSetAttribute(pass1_kernel, cudaFuncAttributeMaxDynamicSharedMemorySize, smem);
    cudaFuncSetAttribute(pass2_kernel, cudaFuncAttributeMaxDynamicSharedMemorySize, smem);

    prep_kernel<<<(FD * 64 + 255) / 256, 256>>>(Wq, W1, W2, B);

    const int nblk = (N + TM - 1) / TM;
    pass1_kernel<<<nblk, NT2, smem>>>(x, seg, E, bq, Wk, bk, N, B);
    pass2_kernel<<<nblk, NT2, smem>>>(seg, E, b1, b2, out, N, B);
}

// round 10
// speedup vs baseline: 4.7991x; 1.0235x over previous
#include <cuda_runtime.h>
#include <cuda_fp16.h>
#include <cstdint>

#define FD 128
#define TM 128
#define NT2 512            // 16 warps (4x4 tiles of 32x32)
#define LDH 68             // smem row stride in words (64 half2 + 4 pad)

// ---------------- device scratch ----------------
__device__ float g_pred[4096];
__device__ float g_cnt[4096];
__device__ uint32_t g_WTq[FD * 64];        // [n][k] transposed, half2-packed
__device__ uint32_t g_WT1[FD * 64];
__device__ uint32_t g_WT2[FD * 64];
__device__ uint32_t g_embedh[500224 * 64]; // embed as half2 words

// ---------------- helpers ----------------
__device__ __forceinline__ uint32_t pack_h2(float a, float b) {
    __half2 h = __floats2half2_rn(a, b);
    return *reinterpret_cast<uint32_t*>(&h);
}
__device__ __forceinline__ float2 unpack_h2(uint32_t u) {
    __half2 h = *reinterpret_cast<__half2*>(&u);
    return __half22float2(h);
}
__device__ __forceinline__ float softplus_fast(float t) {
    return fmaxf(t, 0.0f) + __logf(1.0f + __expf(-fabsf(t)));
}
__device__ __forceinline__ float silu_fast(float v) {
    return __fdividef(v, 1.0f + __expf(-v));
}
__device__ __forceinline__ void mma16(float* c, const uint32_t* a, uint32_t b0, uint32_t b1) {
    asm volatile("mma.sync.aligned.m16n8k16.row.col.f32.f16.f16.f32 "
                 "{%0,%1,%2,%3}, {%4,%5,%6,%7}, {%8,%9}, {%0,%1,%2,%3};"
                 : "+f"(c[0]), "+f"(c[1]), "+f"(c[2]), "+f"(c[3])
                 : "r"(a[0]), "r"(a[1]), "r"(a[2]), "r"(a[3]), "r"(b0), "r"(b1));
}
#define LDSM4(r, addr)                                                        \
    asm volatile("ldmatrix.sync.aligned.m8n8.x4.shared.b16 {%0,%1,%2,%3}, [%4];" \
                 : "=r"((r)[0]), "=r"((r)[1]), "=r"((r)[2]), "=r"((r)[3])     \
                 : "r"(addr))
#define CP_ASYNC16(dst, src) \
    asm volatile("cp.async.cg.shared.global [%0], [%1], 16;" :: "r"(dst), "l"(src) : "memory")
#define CP_COMMIT() asm volatile("cp.async.commit_group;" ::: "memory")
#define CP_WAIT(n)  asm volatile("cp.async.wait_group %0;" :: "n"(n) : "memory")

__device__ __forceinline__ uint32_t smem_u32(const void* p) {
    return (uint32_t)__cvta_generic_to_shared(p);
}

// 128x128x128 tile, warp tile 32x32, ldmatrix fragment loads.
// As[m][k], Bs[n][k] half2-packed at word stride LDH; addresses are smem-u32.
__device__ __forceinline__ void gemm_tile32(uint32_t smA, uint32_t smB,
                                            float acc[2][4][4], int mw, int nw, int lane) {
    #pragma unroll
    for (int i = 0; i < 2; i++)
        #pragma unroll
        for (int j = 0; j < 4; j++)
            #pragma unroll
            for (int e = 0; e < 4; e++) acc[i][j][e] = 0.0f;

    const int l7 = lane & 7;
    const int hi8 = (lane >> 3) & 1;
    const int hi16 = (lane >> 4) & 1;

    // A: matrices m0..m3 of each 16x16 tile -> lanes 0-7/8-15 rows (k-lo), 16-23/24-31 (k-hi)
    uint32_t aAddr0, aAddr1;
    {
        int r = mw + (lane & 15);
        int colw = hi16 ? 4 : 0;
        aAddr0 = smA + (uint32_t)(r * LDH + colw) * 4u;
        aAddr1 = aAddr0 + 16u * LDH * 4u;
    }
    // B: j-pair p covers j=2p,2p+1; lanes 0-15 -> j0 (k-lo/k-hi), 16-31 -> j1
    uint32_t bAddr0, bAddr1;
    {
        int nrow = nw + l7 + (hi16 ? 8 : 0);
        int colw = hi8 ? 4 : 0;
        bAddr0 = smB + (uint32_t)(nrow * LDH + colw) * 4u;
        bAddr1 = bAddr0 + 16u * LDH * 4u;
    }

    #pragma unroll
    for (int ks = 0; ks < 8; ks++) {
        const uint32_t off = (uint32_t)ks * 32u;   // 8 words = 16 halves per k-step
        uint32_t a0[4], a1[4], b0[4], b1[4];
        LDSM4(a0, aAddr0 + off);
        LDSM4(a1, aAddr1 + off);
        LDSM4(b0, bAddr0 + off);
        LDSM4(b1, bAddr1 + off);
        mma16(acc[0][0], a0, b0[0], b0[1]);
        mma16(acc[0][1], a0, b0[2], b0[3]);
        mma16(acc[0][2], a0, b1[0], b1[1]);
        mma16(acc[0][3], a0, b1[2], b1[3]);
        mma16(acc[1][0], a1, b0[0], b0[1]);
        mma16(acc[1][1], a1, b0[2], b0[3]);
        mma16(acc[1][2], a1, b1[0], b1[1]);
        mma16(acc[1][3], a1, b1[2], b1[3]);
    }
}

// ---------------- prep: pack weights + zero accumulators ----------------
__global__ void prep_kernel(const float* __restrict__ Wq, const float* __restrict__ W1,
                            const float* __restrict__ W2, int B) {
    int i = blockIdx.x * blockDim.x + threadIdx.x;
    if (i < FD * 64) {
        int n = i >> 6, kw = i & 63;
        int k0 = kw * 2;
        g_WTq[i] = pack_h2(Wq[k0 * FD + n], Wq[(k0 + 1) * FD + n]);
        g_WT1[i] = pack_h2(W1[k0 * FD + n], W1[(k0 + 1) * FD + n]);
        g_WT2[i] = pack_h2(W2[k0 * FD + n], W2[(k0 + 1) * FD + n]);
    }
    if (i < B) { g_pred[i] = 0.0f; g_cnt[i] = 0.0f; }
}

// cp.async a 128x64-word weight tile into smem (padded rows)
__device__ __forceinline__ void cpa_weight(uint32_t BsAddr, const uint32_t* gw, int tid) {
    #pragma unroll
    for (int k = 0; k < 4; k++) {
        int i = tid + k * NT2;
        int n = i >> 4, q = i & 15;
        CP_ASYNC16(BsAddr + (uint32_t)(n * LDH + q * 4) * 4u, gw + i * 4);
    }
}

// ---------------- pass1: GEMM q + softplus -> embed(half, direct) + segment sums -------
__global__ __launch_bounds__(NT2, 2)
void pass1_kernel(const float* __restrict__ x, const int* __restrict__ seg,
                  const float* __restrict__ E, const float* __restrict__ bq,
                  const float* __restrict__ Wk, const float* __restrict__ bk,
                  int N, int B) {
    extern __shared__ uint32_t dyn[];
    uint32_t* As = dyn;
    const uint32_t AsA = smem_u32(As);
    const uint32_t BsA = AsA + TM * LDH * 4;
    __shared__ float rowsum[TM], eabs_sm[TM];
    __shared__ int segs[TM];
    __shared__ float s_bq[FD], s_Wk[FD], s_bk[FD];

    const int tid = threadIdx.x, wid = tid >> 5, lane = tid & 31;
    const int m0 = blockIdx.x * TM;

    // weight prefetch overlaps x conversion
    cpa_weight(BsA, g_WTq, tid);
    CP_COMMIT();

    if (tid < TM) {
        int gr = min(m0 + tid, N - 1);
        int sb = seg[gr]; sb = min(max(sb, 0), B - 1);
        segs[tid] = sb;
        eabs_sm[tid] = fabsf(E[sb]);
        rowsum[tid] = 0.0f;
        s_bq[tid] = bq[tid]; s_Wk[tid] = Wk[tid]; s_bk[tid] = bk[tid];
    }

    for (int i = tid; i < TM * 32; i += NT2) {
        int r = i >> 5, c = (i & 31) << 2;
        int gr = min(m0 + r, N - 1);
        float4 v = *(const float4*)(x + (size_t)gr * FD + c);
        *(uint2*)(As + r * LDH + (c >> 1)) = make_uint2(pack_h2(v.x, v.y), pack_h2(v.z, v.w));
    }
    CP_WAIT(0);
    __syncthreads();

    const int mw = (wid >> 2) * 32, nw = (wid & 3) * 32;
    float acc[2][4][4];
    gemm_tile32(AsA, BsA, acc, mw, nw, lane);

    // epilogue: softplus + direct embed store + row partial sums
    const int g = lane >> 2, t2 = (lane & 3) << 1;
    #pragma unroll
    for (int i = 0; i < 2; i++) {
        #pragma unroll
        for (int e2 = 0; e2 < 2; e2++) {
            int rl = mw + 16 * i + g + 8 * e2;
            int gr = m0 + rl;
            float ea = eabs_sm[rl];
            float part = 0.0f;
            #pragma unroll
            for (int j = 0; j < 4; j++) {
                int col = nw + 8 * j + t2;
                float q0 = acc[i][j][e2 * 2] + s_bq[col];
                float q1 = acc[i][j][e2 * 2 + 1] + s_bq[col + 1];
                float v0 = softplus_fast(fmaf(ea, s_Wk[col], s_bk[col]) * q0);
                float v1 = softplus_fast(fmaf(ea, s_Wk[col + 1], s_bk[col + 1]) * q1);
                part += v0 + v1;
                if (gr < N)
                    g_embedh[(size_t)gr * 64 + (col >> 1)] = pack_h2(v0, v1);
            }
            part += __shfl_xor_sync(0xffffffffu, part, 1);
            part += __shfl_xor_sync(0xffffffffu, part, 2);
            if ((lane & 3) == 0) atomicAdd(&rowsum[rl], part);
        }
    }
    __syncthreads();

    if (tid < TM) {
        bool head = (tid == 0) || (segs[tid] != segs[tid - 1]);
        if (head && (m0 + tid) < N) {
            int sh = segs[tid];
            float s = 0.0f, c = 0.0f;
            for (int j = tid; j < TM && segs[j] == sh && (m0 + j) < N; j++) {
                s += rowsum[j];
                c += 1.0f;
            }
            atomicAdd(&g_pred[sh], s);
            atomicAdd(&g_cnt[sh], c);
        }
    }
}

// ---------------- pass2: load embed, 2 chained GEMMs, W2 double-buffered ----------------
__global__ __launch_bounds__(NT2, 2)
void pass2_kernel(const int* __restrict__ seg, const float* __restrict__ E,
                  const float* __restrict__ b1, const float* __restrict__ b2,
                  float* __restrict__ out, int N, int B) {
    extern __shared__ uint32_t dyn[];
    uint32_t* As = dyn;
    const uint32_t AsA = smem_u32(As);
    const uint32_t BsA  = AsA + TM * LDH * 4;      // W1
    const uint32_t Bs2A = BsA + TM * LDH * 4;      // W2
    __shared__ float dval[TM];
    __shared__ float s_b1[FD], s_b2[FD];

    const int tid = threadIdx.x, wid = tid >> 5, lane = tid & 31;
    const int m0 = blockIdx.x * TM;

    // prefetch both weight tiles; W1 in group 0, W2 in group 1
    cpa_weight(BsA, g_WT1, tid);
    CP_COMMIT();
    cpa_weight(Bs2A, g_WT2, tid);
    CP_COMMIT();

    if (tid < TM) {
        int gr = min(m0 + tid, N - 1);
        int sb = seg[gr]; sb = min(max(sb, 0), B - 1);
        dval[tid] = (E[sb] - g_pred[sb]) / g_cnt[sb] * (1.0f / 128.0f);
        s_b1[tid] = b1[tid]; s_b2[tid] = b2[tid];
    }
    __syncthreads();   // dval ready for As build

    // load embed, build silu(embed + d) -> As (overlaps weight cp.asyncs)
    for (int i = tid; i < TM * 16; i += NT2) {
        int r = i >> 4, wq = (i & 15) << 2;
        int gr = min(m0 + r, N - 1);
        uint4 u = *(const uint4*)(g_embedh + (size_t)gr * 64 + wq);
        float dd = dval[r];
        uint32_t w[4] = {u.x, u.y, u.z, u.w};
        #pragma unroll
        for (int q = 0; q < 4; q++) {
            float2 e = unpack_h2(w[q]);
            As[r * LDH + wq + q] = pack_h2(silu_fast(e.x + dd), silu_fast(e.y + dd));
        }
    }
    CP_WAIT(1);        // W1 complete (W2 may still be in flight)
    __syncthreads();

    const int mw = (wid >> 2) * 32, nw = (wid & 3) * 32;
    const int g = lane >> 2, t2 = (lane & 3) << 1;
    float acc[2][4][4];

    // GEMM2: h1 = silu(scale) @ W1
    gemm_tile32(AsA, BsA, acc, mw, nw, lane);

    #pragma unroll
    for (int i = 0; i < 2; i++)
        #pragma unroll
        for (int j = 0; j < 4; j++)
            #pragma unroll
            for (int e = 0; e < 4; e++) {
                int col = nw + 8 * j + t2 + (e & 1);
                acc[i][j][e] = silu_fast(acc[i][j][e] + s_b1[col]);
            }
    CP_WAIT(0);        // W2 complete
    __syncthreads();   // all warps done reading As

    #pragma unroll
    for (int i = 0; i < 2; i++)
        #pragma unroll
        for (int e2 = 0; e2 < 2; e2++) {
            int rl = mw + 16 * i + g + 8 * e2;
            #pragma unroll
            for (int j = 0; j < 4; j++)
                As[rl * LDH + ((nw + 8 * j + t2) >> 1)] =
                    pack_h2(acc[i][j][e2 * 2], acc[i][j][e2 * 2 + 1]);
        }
    __syncthreads();

    // GEMM3: h2 = h @ W2
    gemm_tile32(AsA, Bs2A, acc, mw, nw, lane);

    // direct fragment epilogue: out = (embed + d) + h2 + b2
    #pragma unroll
    for (int i = 0; i < 2; i++)
        #pragma unroll
        for (int e2 = 0; e2 < 2; e2++) {
            int rl = mw + 16 * i + g + 8 * e2;
            int gr = m0 + rl;
            if (gr < N) {
                float dd = dval[rl];
                #pragma unroll
                for (int j = 0; j < 4; j++) {
                    int col = nw + 8 * j + t2;
                    float2 e = unpack_h2(g_embedh[(size_t)gr * 64 + (col >> 1)]);
                    float2 o;
                    o.x = e.x + dd + acc[i][j][e2 * 2]     + s_b2[col];
                    o.y = e.y + dd + acc[i][j][e2 * 2 + 1] + s_b2[col + 1];
                    *(float2*)(out + (size_t)gr * FD + col) = o;
                }
            }
        }
}

// ---------------------------------------------------------------------------
extern "C" void kernel_launch(void* const* d_in, const int* in_sizes, int n_in,
                              void* d_out, int out_size) {
    const float* x   = (const float*)d_in[0];
    const float* E   = (const float*)d_in[1];
    const int*   seg = (const int*)d_in[3];
    const float* Wq  = (const float*)d_in[4];
    const float* bq  = (const float*)d_in[5];
    const float* Wk  = (const float*)d_in[6];
    const float* bk  = (const float*)d_in[7];
    const float* W1  = (const float*)d_in[8];
    const float* b1  = (const float*)d_in[9];
    const float* W2  = (const float*)d_in[10];
    const float* b2  = (const float*)d_in[11];
    float* out = (float*)d_out;

    const int N = in_sizes[0] / FD;
    const int B = in_sizes[1];

    const int smem1 = 2 * TM * LDH * 4;   // 69632
    const int smem2 = 3 * TM * LDH * 4;   // 104448
    cudaFuncSetAttribute(pass1_kernel, cudaFuncAttributeMaxDynamicSharedMemorySize, smem1);
    cudaFuncSetAttribute(pass2_kernel, cudaFuncAttributeMaxDynamicSharedMemorySize, smem2);

    prep_kernel<<<(FD * 64 + 255) / 256, 256>>>(Wq, W1, W2, B);

    const int nblk = (N + TM - 1) / TM;
    pass1_kernel<<<nblk, NT2, smem1>>>(x, seg, E, bq, Wk, bk, N, B);
    pass2_kernel<<<nblk, NT2, smem2>>>(seg, E, b1, b2, out, N, B);
}